// round 10
// baseline (speedup 1.0000x reference)
#include <cuda_runtime.h>
#include <cuda_fp16.h>
#include <math.h>
#include <stdint.h>

// Problem constants
#define NB 8
#define LQ 1024
#define SK 4096
#define DD 512
#define MQ  (NB * LQ)   // 8192
#define MKV (NB * SK)   // 32768
#define LN_EPS 1e-5f

// ---------------------------------------------------------------------------
// Scratch (device globals)
// ---------------------------------------------------------------------------
__device__ __half g_xh  [(size_t)MQ  * DD];
__device__ __half g_srch[(size_t)MKV * DD];
__device__ __half g_qh  [(size_t)MQ  * DD];
__device__ __half g_kh  [(size_t)MKV * DD];
__device__ __half g_vh  [(size_t)MKV * DD];
__device__ __half g_vt  [(size_t)MKV * DD];          // per batch [D,S]
__device__ __half g_sch [(size_t)NB * LQ * SK];      // shifted dist -> attn (in place)
__device__ __half g_msgh[(size_t)MQ * DD];
__device__ __half g_hh  [(size_t)MQ * 2 * DD];
__device__ __half g_fc1h[(size_t)MQ * 2 * DD];
__device__ __half g_wqt [DD * DD];
__device__ __half g_wkt [DD * DD];
__device__ __half g_wvt [DD * DD];
__device__ __half g_wmt [DD * DD];
__device__ __half g_w1t [2 * DD * 2 * DD];
__device__ __half g_w2t [DD * 2 * DD];
__device__ float  g_tmp [(size_t)MQ * DD];
__device__ float  g_q2  [MQ];
__device__ float  g_k2  [MKV];
__device__ float  g_k2m [NB];

// ---------------------------------------------------------------------------
// PTX helpers (base compute_103 only)
// ---------------------------------------------------------------------------
__device__ __forceinline__ uint32_t cvta_smem(const void* p) {
    uint32_t a;
    asm("{ .reg .u64 t; cvta.to.shared.u64 t, %1; cvt.u32.u64 %0, t; }"
        : "=r"(a) : "l"(p));
    return a;
}
__device__ __forceinline__ void cp16(uint32_t d, const void* s) {
    asm volatile("cp.async.cg.shared.global [%0], [%1], 16;"
                 :: "r"(d), "l"(s));
}
__device__ __forceinline__ void cp_commit() {
    asm volatile("cp.async.commit_group;" ::: "memory");
}
template <int N>
__device__ __forceinline__ void cp_wait() {
    asm volatile("cp.async.wait_group %0;" :: "n"(N) : "memory");
}
__device__ __forceinline__ void ldsm4(uint32_t* r, uint32_t addr) {
    asm volatile("ldmatrix.sync.aligned.m8n8.x4.shared.b16 {%0,%1,%2,%3}, [%4];"
        : "=r"(r[0]), "=r"(r[1]), "=r"(r[2]), "=r"(r[3]) : "r"(addr));
}
__device__ __forceinline__ void mma_fp16(float* c, const uint32_t* a,
                                         const uint32_t* b) {
    asm volatile(
        "mma.sync.aligned.m16n8k16.row.col.f32.f16.f16.f32 "
        "{%0,%1,%2,%3}, {%4,%5,%6,%7}, {%8,%9}, {%0,%1,%2,%3};"
        : "+f"(c[0]), "+f"(c[1]), "+f"(c[2]), "+f"(c[3])
        : "r"(a[0]), "r"(a[1]), "r"(a[2]), "r"(a[3]),
          "r"(b[0]), "r"(b[1]));
}

// ---------------------------------------------------------------------------
// fp16 NT GEMM: C[M,Nc] = A[M,K] @ B[Nc,K]^T   (fp32 accumulate)
// Block tile 128x256x32, 8 warps (2x4) of 64x64 warp tiles, 3-stage cp.async,
// ldmatrix.x4 fragment loads. M%128==0, Nc%256==0, K%32==0, K>=64.
// DIST: C = sqrt(max(q2[r]+k2[c]-2acc,0)) - sqrt(q2[r]+k2m[z])  (fp16 store;
//       per-row shift is softmax-invariant, keeps values near 0 for precision)
// ---------------------------------------------------------------------------
constexpr int ASTR = 40;                 // halfs per smem row
constexpr int AT_H = 128 * ASTR;         // 5120 halfs
constexpr int BT_H = 256 * ASTR;         // 10240 halfs
constexpr int STAGE_H = AT_H + BT_H;     // 15360 halfs = 30720 B
#define SMEM_GEMM (3 * STAGE_H * 2)      // 92160 B

template <bool RELU, typename TOUT, bool DIST>
__global__ __launch_bounds__(256, 1) void hgemm(
    const __half* __restrict__ A, const __half* __restrict__ B,
    TOUT* __restrict__ C, int M, int Nc, int K,
    long sA, long sB, long sC,
    const float* __restrict__ q2, const float* __restrict__ k2,
    const float* __restrict__ k2m)
{
    extern __shared__ __align__(16) __half smh[];
    A += (long)blockIdx.z * sA;
    B += (long)blockIdx.z * sB;
    C += (long)blockIdx.z * sC;
    const float* q2p = DIST ? q2 + (long)blockIdx.z * LQ : nullptr;
    const float* k2p = DIST ? k2 + (long)blockIdx.z * SK : nullptr;

    const int tid = threadIdx.x, lane = tid & 31, wid = tid >> 5;
    const int wm = wid >> 2, wn = wid & 3;       // 2 x 4 warp grid
    const int row0 = blockIdx.y * 128, col0 = blockIdx.x * 256;
    const uint32_t smb = cvta_smem(smh);

    float acc[4][8][4];
    #pragma unroll
    for (int i = 0; i < 4; i++)
        #pragma unroll
        for (int j = 0; j < 8; j++)
            #pragma unroll
            for (int l = 0; l < 4; l++) acc[i][j][l] = 0.f;

    const int nt = K >> 5;

    auto load_stage = [&](int s, int t) {
        const int k0 = t << 5;
        uint32_t sa = smb + (uint32_t)(s * STAGE_H * 2);
        const __half* ga = A + (long)row0 * K + k0;
        #pragma unroll
        for (int i = 0; i < 2; i++) {
            int id = tid + (i << 8);
            int r = id >> 2, c = id & 3;
            cp16(sa + (uint32_t)(r * 80 + c * 16), ga + (long)r * K + (c << 3));
        }
        uint32_t sb = smb + (uint32_t)((s * STAGE_H + AT_H) * 2);
        const __half* gb = B + (long)col0 * K + k0;
        #pragma unroll
        for (int i = 0; i < 4; i++) {
            int id = tid + (i << 8);
            int r = id >> 2, c = id & 3;
            cp16(sb + (uint32_t)(r * 80 + c * 16), gb + (long)r * K + (c << 3));
        }
        cp_commit();
    };

    const int a_row = (lane & 7) + ((lane >> 3) & 1) * 8;
    const int a_kof = (lane >> 4) * 8;
    const int b_nof = (lane & 7) + ((lane >> 4) ? 8 : 0);
    const int b_kof = ((lane >> 3) & 1) * 8;

    load_stage(0, 0);
    load_stage(1, 1);

    for (int t = 0; t < nt; t++) {
        const int s = t % 3;
        if (t + 1 < nt) cp_wait<1>(); else cp_wait<0>();
        __syncthreads();
        if (t + 2 < nt) load_stage((t + 2) % 3, t + 2);

        const uint32_t sa = smb + (uint32_t)(s * STAGE_H * 2);
        const uint32_t sb = smb + (uint32_t)((s * STAGE_H + AT_H) * 2);

        #pragma unroll
        for (int ks = 0; ks < 2; ks++) {
            uint32_t af[4][4];
            #pragma unroll
            for (int ma = 0; ma < 4; ma++) {
                uint32_t ad = sa + (uint32_t)(((wm * 64 + ma * 16 + a_row) * ASTR
                                               + ks * 16 + a_kof) * 2);
                ldsm4(af[ma], ad);
            }
            uint32_t bf[8][2];
            #pragma unroll
            for (int p = 0; p < 4; p++) {
                uint32_t bd = sb + (uint32_t)(((wn * 64 + p * 16 + b_nof) * ASTR
                                               + ks * 16 + b_kof) * 2);
                ldsm4(&bf[2 * p][0], bd);
            }
            #pragma unroll
            for (int ma = 0; ma < 4; ma++)
                #pragma unroll
                for (int na = 0; na < 8; na++)
                    mma_fp16(acc[ma][na], af[ma], bf[na]);
        }
        __syncthreads();
    }

    // Epilogue
    float km = DIST ? k2m[blockIdx.z] : 0.f;
    #pragma unroll
    for (int ma = 0; ma < 4; ma++) {
        int r = row0 + wm * 64 + ma * 16 + (lane >> 2);
        float q2v0 = 0.f, q2v1 = 0.f, cr0 = 0.f, cr1 = 0.f;
        if (DIST) {
            q2v0 = q2p[r]; q2v1 = q2p[r + 8];
            cr0 = sqrtf(q2v0 + km); cr1 = sqrtf(q2v1 + km);
        }
        #pragma unroll
        for (int na = 0; na < 8; na++) {
            int cc = col0 + wn * 64 + na * 8 + 2 * (lane & 3);
            float c0 = acc[ma][na][0], c1 = acc[ma][na][1];
            float c2 = acc[ma][na][2], c3 = acc[ma][na][3];
            if (DIST) {
                float k2v0 = k2p[cc], k2v1 = k2p[cc + 1];
                c0 = sqrtf(fmaxf(q2v0 + k2v0 - 2.f * c0, 0.f)) - cr0;
                c1 = sqrtf(fmaxf(q2v0 + k2v1 - 2.f * c1, 0.f)) - cr0;
                c2 = sqrtf(fmaxf(q2v1 + k2v0 - 2.f * c2, 0.f)) - cr1;
                c3 = sqrtf(fmaxf(q2v1 + k2v1 - 2.f * c3, 0.f)) - cr1;
            }
            if (RELU) {
                c0 = fmaxf(c0, 0.f); c1 = fmaxf(c1, 0.f);
                c2 = fmaxf(c2, 0.f); c3 = fmaxf(c3, 0.f);
            }
            if (sizeof(TOUT) == 2) {
                *(__half2*)((__half*)C + (long)r * Nc + cc) =
                    __floats2half2_rn(c0, c1);
                *(__half2*)((__half*)C + (long)(r + 8) * Nc + cc) =
                    __floats2half2_rn(c2, c3);
            } else {
                *(float2*)((float*)C + (long)r * Nc + cc) = make_float2(c0, c1);
                *(float2*)((float*)C + (long)(r + 8) * Nc + cc) = make_float2(c2, c3);
            }
        }
    }
}

// ---------------------------------------------------------------------------
// Conversion / transpose kernels
// ---------------------------------------------------------------------------
__global__ __launch_bounds__(256) void conv_f2h(
    const float* __restrict__ in, __half* __restrict__ out)
{
    long i = ((long)blockIdx.x * 256 + threadIdx.x) * 4;
    float4 v = *(const float4*)(in + i);
    *(__half2*)(out + i)     = __floats2half2_rn(v.x, v.y);
    *(__half2*)(out + i + 2) = __floats2half2_rn(v.z, v.w);
}

// x -> xh, and also into the left half of h = [x | ln1] (fp16)
__global__ __launch_bounds__(256) void conv_x_pack(
    const float* __restrict__ in, __half* __restrict__ xh,
    __half* __restrict__ hh)
{
    long i = ((long)blockIdx.x * 256 + threadIdx.x) * 4;
    float4 v = *(const float4*)(in + i);
    __half2 h0 = __floats2half2_rn(v.x, v.y);
    __half2 h1 = __floats2half2_rn(v.z, v.w);
    *(__half2*)(xh + i) = h0;
    *(__half2*)(xh + i + 2) = h1;
    long row = i >> 9;          // /512
    int col = (int)(i & 511);
    __half* hr = hh + row * (2 * DD) + col;
    *(__half2*)hr = h0;
    *(__half2*)(hr + 2) = h1;
}

__global__ void trans_f2h(const float* __restrict__ in, __half* __restrict__ out,
                          int R, int C)
{
    __shared__ float t[32][33];
    int c0 = blockIdx.x * 32, r0 = blockIdx.y * 32;
    #pragma unroll
    for (int i = threadIdx.y; i < 32; i += 8)
        t[i][threadIdx.x] = in[(long)(r0 + i) * C + c0 + threadIdx.x];
    __syncthreads();
    #pragma unroll
    for (int i = threadIdx.y; i < 32; i += 8)
        out[(long)(c0 + i) * R + r0 + threadIdx.x] = __float2half_rn(t[threadIdx.x][i]);
}

__global__ void trans_h2h(const __half* __restrict__ in, __half* __restrict__ out,
                          int R, int C)
{
    __shared__ __half t[32][33];
    long bi = (long)blockIdx.z * R * C;
    int c0 = blockIdx.x * 32, r0 = blockIdx.y * 32;
    #pragma unroll
    for (int i = threadIdx.y; i < 32; i += 8)
        t[i][threadIdx.x] = in[bi + (long)(r0 + i) * C + c0 + threadIdx.x];
    __syncthreads();
    #pragma unroll
    for (int i = threadIdx.y; i < 32; i += 8)
        out[bi + (long)(c0 + i) * R + r0 + threadIdx.x] = t[threadIdx.x][i];
}

// ---------------------------------------------------------------------------
// Reductions
// ---------------------------------------------------------------------------
__device__ __forceinline__ float warpSum(float v) {
    #pragma unroll
    for (int o = 16; o > 0; o >>= 1) v += __shfl_xor_sync(0xffffffffu, v, o);
    return v;
}
__device__ __forceinline__ float warpMax(float v) {
    #pragma unroll
    for (int o = 16; o > 0; o >>= 1) v = fmaxf(v, __shfl_xor_sync(0xffffffffu, v, o));
    return v;
}
__device__ float blockSum(float v) {
    __shared__ float sh[8];
    __shared__ float tot;
    __syncthreads();
    int lane = threadIdx.x & 31, w = threadIdx.x >> 5;
    v = warpSum(v);
    if (lane == 0) sh[w] = v;
    __syncthreads();
    if (w == 0) {
        float t = (threadIdx.x < (blockDim.x >> 5)) ? sh[threadIdx.x] : 0.f;
        t = warpSum(t);
        if (threadIdx.x == 0) tot = t;
    }
    __syncthreads();
    return tot;
}
__device__ float blockMax(float v) {
    __shared__ float sh[8];
    __shared__ float tot;
    __syncthreads();
    int lane = threadIdx.x & 31, w = threadIdx.x >> 5;
    v = warpMax(v);
    if (lane == 0) sh[w] = v;
    __syncthreads();
    if (w == 0) {
        float t = (threadIdx.x < (blockDim.x >> 5)) ? sh[threadIdx.x] : -INFINITY;
        t = warpMax(t);
        if (threadIdx.x == 0) tot = t;
    }
    __syncthreads();
    return tot;
}

// ---------------------------------------------------------------------------
// Elementwise kernels
// ---------------------------------------------------------------------------
__global__ __launch_bounds__(256) void rownorm_h(
    const __half* __restrict__ X, float* __restrict__ out)
{
    const __half2* x = (const __half2*)(X + (long)blockIdx.x * DD);
    float2 f = __half22float2(x[threadIdx.x]);
    float s = blockSum(f.x * f.x + f.y * f.y);
    if (threadIdx.x == 0) out[blockIdx.x] = s;
}

// per-batch mean of k2 (deterministic block reduction, one block per batch)
__global__ __launch_bounds__(256) void k2mean_k(
    const float* __restrict__ k2, float* __restrict__ k2m)
{
    const float* kk = k2 + (long)blockIdx.x * SK;
    float s = 0.f;
    #pragma unroll
    for (int i = 0; i < SK / 256; i++) s += kk[threadIdx.x + i * 256];
    s = blockSum(s);
    if (threadIdx.x == 0) k2m[blockIdx.x] = s * (1.f / SK);
}

// softmax over fp16 shifted-dist row (in place)
__global__ __launch_bounds__(256) void softmax_k(__half* __restrict__ dist)
{
    __half2* row = (__half2*)(dist + (long)blockIdx.x * SK);

    float d[16];
    float mx = -INFINITY;
    #pragma unroll
    for (int i = 0; i < 8; i++) {
        int j = threadIdx.x + i * 256;
        float2 f = __half22float2(row[j]);
        d[2 * i] = f.x; d[2 * i + 1] = f.y;
        mx = fmaxf(mx, fmaxf(f.x, f.y));
    }
    mx = blockMax(mx);

    float s = 0.f;
    #pragma unroll
    for (int i = 0; i < 16; i++) {
        d[i] = expf(d[i] - mx);
        s += d[i];
    }
    s = blockSum(s);
    float inv = 1.f / s;
    #pragma unroll
    for (int i = 0; i < 8; i++) {
        int j = threadIdx.x + i * 256;
        row[j] = __floats2half2_rn(d[2 * i] * inv, d[2 * i + 1] * inv);
    }
}

// LayerNorm(mm) -> right half of h only (left half pre-filled by conv_x_pack)
__global__ __launch_bounds__(256) void ln1_pack_k(
    const float* __restrict__ mm,
    const float* __restrict__ g, const float* __restrict__ b,
    __half* __restrict__ h)
{
    const int row = blockIdx.x;
    const float* m = mm + (long)row * DD;
    const int c0 = threadIdx.x, c1 = threadIdx.x + 256;
    float v0 = m[c0], v1 = m[c1];
    float mean = blockSum(v0 + v1) * (1.f / DD);
    float var  = blockSum(v0 * v0 + v1 * v1) * (1.f / DD) - mean * mean;
    float inv = rsqrtf(var + LN_EPS);

    __half* hr = h + (long)row * (2 * DD);
    hr[DD + c0] = __float2half_rn((v0 - mean) * inv * g[c0] + b[c0]);
    hr[DD + c1] = __float2half_rn((v1 - mean) * inv * g[c1] + b[c1]);
}

__global__ __launch_bounds__(256) void ln2_add_k(
    const float* __restrict__ t, const float* __restrict__ x,
    const float* __restrict__ g, const float* __restrict__ b,
    float* __restrict__ out)
{
    const int row = blockIdx.x;
    const float* tr = t + (long)row * DD;
    const int c0 = threadIdx.x, c1 = threadIdx.x + 256;
    float v0 = tr[c0], v1 = tr[c1];
    float mean = blockSum(v0 + v1) * (1.f / DD);
    float var  = blockSum(v0 * v0 + v1 * v1) * (1.f / DD) - mean * mean;
    float inv = rsqrtf(var + LN_EPS);

    const float* xr = x + (long)row * DD;
    float* orow = out + (long)row * DD;
    orow[c0] = xr[c0] + (v0 - mean) * inv * g[c0] + b[c0];
    orow[c1] = xr[c1] + (v1 - mean) * inv * g[c1] + b[c1];
}

// ---------------------------------------------------------------------------
// Launch
// ---------------------------------------------------------------------------
extern "C" void kernel_launch(void* const* d_in, const int* in_sizes, int n_in,
                              void* d_out, int out_size)
{
    const float* x   = (const float*)d_in[0];
    const float* src = (const float*)d_in[1];
    const float* Wq  = (const float*)d_in[2];
    const float* Wk  = (const float*)d_in[3];
    const float* Wv  = (const float*)d_in[4];
    const float* Wm  = (const float*)d_in[5];
    const float* W1  = (const float*)d_in[6];
    const float* W2  = (const float*)d_in[7];
    const float* g1  = (const float*)d_in[8];
    const float* b1  = (const float*)d_in[9];
    const float* g2  = (const float*)d_in[10];
    const float* b2  = (const float*)d_in[11];
    float* out = (float*)d_out;

    __half *xh, *srch, *qh, *kh, *vh, *vt, *sch, *msgh, *hh, *fc1h;
    __half *wqt, *wkt, *wvt, *wmt, *w1t, *w2t;
    float *tmp, *q2, *k2, *k2m;
    cudaGetSymbolAddress((void**)&xh,   g_xh);
    cudaGetSymbolAddress((void**)&srch, g_srch);
    cudaGetSymbolAddress((void**)&qh,   g_qh);
    cudaGetSymbolAddress((void**)&kh,   g_kh);
    cudaGetSymbolAddress((void**)&vh,   g_vh);
    cudaGetSymbolAddress((void**)&vt,   g_vt);
    cudaGetSymbolAddress((void**)&sch,  g_sch);
    cudaGetSymbolAddress((void**)&msgh, g_msgh);
    cudaGetSymbolAddress((void**)&hh,   g_hh);
    cudaGetSymbolAddress((void**)&fc1h, g_fc1h);
    cudaGetSymbolAddress((void**)&wqt,  g_wqt);
    cudaGetSymbolAddress((void**)&wkt,  g_wkt);
    cudaGetSymbolAddress((void**)&wvt,  g_wvt);
    cudaGetSymbolAddress((void**)&wmt,  g_wmt);
    cudaGetSymbolAddress((void**)&w1t,  g_w1t);
    cudaGetSymbolAddress((void**)&w2t,  g_w2t);
    cudaGetSymbolAddress((void**)&tmp,  g_tmp);
    cudaGetSymbolAddress((void**)&q2,   g_q2);
    cudaGetSymbolAddress((void**)&k2,   g_k2);
    cudaGetSymbolAddress((void**)&k2m,  g_k2m);

    cudaFuncSetAttribute((const void*)hgemm<false, __half, false>,
        cudaFuncAttributeMaxDynamicSharedMemorySize, SMEM_GEMM);
    cudaFuncSetAttribute((const void*)hgemm<false, float, false>,
        cudaFuncAttributeMaxDynamicSharedMemorySize, SMEM_GEMM);
    cudaFuncSetAttribute((const void*)hgemm<true, __half, false>,
        cudaFuncAttributeMaxDynamicSharedMemorySize, SMEM_GEMM);
    cudaFuncSetAttribute((const void*)hgemm<false, __half, true>,
        cudaFuncAttributeMaxDynamicSharedMemorySize, SMEM_GEMM);

    dim3 t32(32, 8, 1);

    // (1) src -> fp16
    conv_f2h<<<(MKV * DD) / 1024, 256>>>(src, srch);
    // (2) x -> fp16 (+ left half of h)
    conv_x_pack<<<(MQ * DD) / 1024, 256>>>(x, xh, hh);
    // (3) Wk^T
    trans_f2h<<<dim3(DD / 32, DD / 32), t32>>>(Wk, wkt, DD, DD);
    // (4) k projection
    hgemm<false, __half, false><<<dim3(DD / 256, MKV / 128, 1), 256, SMEM_GEMM>>>(
        srch, wkt, kh, MKV, DD, DD, 0, 0, 0, nullptr, nullptr, nullptr);
    // (5) Wq^T
    trans_f2h<<<dim3(DD / 32, DD / 32), t32>>>(Wq, wqt, DD, DD);
    // (6) q projection
    hgemm<false, __half, false><<<dim3(DD / 256, MQ / 128, 1), 256, SMEM_GEMM>>>(
        xh, wqt, qh, MQ, DD, DD, 0, 0, 0, nullptr, nullptr, nullptr);
    // (7) Wv^T
    trans_f2h<<<dim3(DD / 32, DD / 32), t32>>>(Wv, wvt, DD, DD);
    // (8) v projection
    hgemm<false, __half, false><<<dim3(DD / 256, MKV / 128, 1), 256, SMEM_GEMM>>>(
        srch, wvt, vh, MKV, DD, DD, 0, 0, 0, nullptr, nullptr, nullptr);

    // Row squared norms (of the quantized fp16 values the MMAs consume)
    rownorm_h<<<MQ, 256>>>(qh, q2);
    rownorm_h<<<MKV, 256>>>(kh, k2);
    k2mean_k<<<NB, 256>>>(k2, k2m);

    // Remaining weight transposes
    trans_f2h<<<dim3(DD / 32, DD / 32), t32>>>(Wm, wmt, DD, DD);
    trans_f2h<<<dim3(2 * DD / 32, 2 * DD / 32), t32>>>(W1, w1t, 2 * DD, 2 * DD);
    trans_f2h<<<dim3(DD / 32, 2 * DD / 32), t32>>>(W2, w2t, 2 * DD, DD);

    // v transpose per batch: [S,D] -> [D,S]
    trans_h2h<<<dim3(DD / 32, SK / 32, NB), t32>>>(vh, vt, SK, DD);

    // Shifted dist fused into scores GEMM (fp16 out)
    hgemm<false, __half, true><<<dim3(SK / 256, LQ / 128, NB), 256, SMEM_GEMM>>>(
        qh, kh, sch, LQ, SK, DD,
        (long)LQ * DD, (long)SK * DD, (long)LQ * SK, q2, k2, k2m);

    // softmax in place -> fp16 attn
    softmax_k<<<MQ, 256>>>(sch);

    // message = attn @ v  (NT with vt, fp16 out)
    hgemm<false, __half, false><<<dim3(DD / 256, LQ / 128, NB), 256, SMEM_GEMM>>>(
        sch, vt, msgh, LQ, DD, SK,
        (long)LQ * SK, (long)DD * SK, (long)LQ * DD, nullptr, nullptr, nullptr);

    // mm = message @ Wm (fp32 out)
    hgemm<false, float, false><<<dim3(DD / 256, MQ / 128, 1), 256, SMEM_GEMM>>>(
        msgh, wmt, tmp, MQ, DD, DD, 0, 0, 0, nullptr, nullptr, nullptr);

    // h right half = LayerNorm(mm)
    ln1_pack_k<<<MQ, 256>>>(tmp, g1, b1, hh);

    // fc1 = relu(h @ W1) (fp16 out)
    hgemm<true, __half, false><<<dim3(2 * DD / 256, MQ / 128, 1), 256, SMEM_GEMM>>>(
        hh, w1t, fc1h, MQ, 2 * DD, 2 * DD, 0, 0, 0, nullptr, nullptr, nullptr);

    // fc2 = fc1 @ W2 (fp32 out)
    hgemm<false, float, false><<<dim3(DD / 256, MQ / 128, 1), 256, SMEM_GEMM>>>(
        fc1h, w2t, tmp, MQ, DD, 2 * DD, 0, 0, 0, nullptr, nullptr, nullptr);

    // out = x + LayerNorm(fc2)
    ln2_add_k<<<MQ, 256>>>(tmp, x, g2, b2, out);
}

// round 12
// speedup vs baseline: 1.0968x; 1.0968x over previous
#include <cuda_runtime.h>
#include <cuda_fp16.h>
#include <math.h>
#include <stdint.h>

// Problem constants
#define NB 8
#define LQ 1024
#define SK 4096
#define DD 512
#define MQ  (NB * LQ)   // 8192
#define MKV (NB * SK)   // 32768
#define LN_EPS 1e-5f

// ---------------------------------------------------------------------------
// Scratch (device globals)
// ---------------------------------------------------------------------------
__device__ __half g_xh  [(size_t)MQ  * DD];
__device__ __half g_srch[(size_t)MKV * DD];
__device__ __half g_qh  [(size_t)MQ  * DD];
__device__ __half g_kh  [(size_t)MKV * DD];
__device__ __half g_vh  [(size_t)MKV * DD];
__device__ __half g_vt  [(size_t)MKV * DD];          // per batch [D,S]
__device__ __half g_sch [(size_t)NB * LQ * SK];      // shifted dist -> attn (in place)
__device__ __half g_msgh[(size_t)MQ * DD];
__device__ __half g_hh  [(size_t)MQ * 2 * DD];
__device__ __half g_fc1h[(size_t)MQ * 2 * DD];
__device__ __half g_wqt [DD * DD];
__device__ __half g_wkt [DD * DD];
__device__ __half g_wvt [DD * DD];
__device__ __half g_wmt [DD * DD];
__device__ __half g_w1t [2 * DD * 2 * DD];
__device__ __half g_w2t [DD * 2 * DD];
__device__ float  g_tmp [(size_t)MQ * DD];
__device__ float  g_q2  [MQ];
__device__ float  g_k2  [MKV];
__device__ float  g_k2m [NB];

// ---------------------------------------------------------------------------
// PTX helpers (base compute_103 only)
// ---------------------------------------------------------------------------
__device__ __forceinline__ uint32_t cvta_smem(const void* p) {
    uint32_t a;
    asm("{ .reg .u64 t; cvta.to.shared.u64 t, %1; cvt.u32.u64 %0, t; }"
        : "=r"(a) : "l"(p));
    return a;
}
__device__ __forceinline__ void cp16(uint32_t d, const void* s) {
    asm volatile("cp.async.cg.shared.global [%0], [%1], 16;"
                 :: "r"(d), "l"(s));
}
__device__ __forceinline__ void cp_commit() {
    asm volatile("cp.async.commit_group;" ::: "memory");
}
template <int N>
__device__ __forceinline__ void cp_wait() {
    asm volatile("cp.async.wait_group %0;" :: "n"(N) : "memory");
}
__device__ __forceinline__ void ldsm4(uint32_t* r, uint32_t addr) {
    asm volatile("ldmatrix.sync.aligned.m8n8.x4.shared.b16 {%0,%1,%2,%3}, [%4];"
        : "=r"(r[0]), "=r"(r[1]), "=r"(r[2]), "=r"(r[3]) : "r"(addr));
}
__device__ __forceinline__ void mma_fp16(float* c, const uint32_t* a,
                                         const uint32_t* b) {
    asm volatile(
        "mma.sync.aligned.m16n8k16.row.col.f32.f16.f16.f32 "
        "{%0,%1,%2,%3}, {%4,%5,%6,%7}, {%8,%9}, {%0,%1,%2,%3};"
        : "+f"(c[0]), "+f"(c[1]), "+f"(c[2]), "+f"(c[3])
        : "r"(a[0]), "r"(a[1]), "r"(a[2]), "r"(a[3]),
          "r"(b[0]), "r"(b[1]));
}

// ---------------------------------------------------------------------------
// fp16 NT GEMM: C[M,Nc] = A[M,K] @ B[Nc,K]^T   (fp32 accumulate)
// Block tile 128x128x32, 8 warps (2x4) of 64x32 warp tiles, 3-stage cp.async,
// ldmatrix.x4 fragment loads, 2 CTAs per SM for latency hiding.
// M%128==0, Nc%128==0, K%32==0, K>=64.
// DIST: C = sqrt(max(q2[r]+k2[c]-2acc,0)) - sqrt(q2[r]+k2m[z])  (fp16 store)
// ---------------------------------------------------------------------------
constexpr int ASTR = 40;                 // halfs per smem row
constexpr int AT_H = 128 * ASTR;         // 5120 halfs
constexpr int BT_H = 128 * ASTR;         // 5120 halfs
constexpr int STAGE_H = AT_H + BT_H;     // 10240 halfs = 20480 B
#define SMEM_GEMM (3 * STAGE_H * 2)      // 61440 B

template <bool RELU, typename TOUT, bool DIST>
__global__ __launch_bounds__(256, 2) void hgemm(
    const __half* __restrict__ A, const __half* __restrict__ B,
    TOUT* __restrict__ C, int M, int Nc, int K,
    long sA, long sB, long sC,
    const float* __restrict__ q2, const float* __restrict__ k2,
    const float* __restrict__ k2m)
{
    extern __shared__ __align__(16) __half smh[];
    A += (long)blockIdx.z * sA;
    B += (long)blockIdx.z * sB;
    C += (long)blockIdx.z * sC;
    const float* q2p = DIST ? q2 + (long)blockIdx.z * LQ : nullptr;
    const float* k2p = DIST ? k2 + (long)blockIdx.z * SK : nullptr;

    const int tid = threadIdx.x, lane = tid & 31, wid = tid >> 5;
    const int wm = wid >> 2, wn = wid & 3;       // 2 x 4 warp grid
    const int row0 = blockIdx.y * 128, col0 = blockIdx.x * 128;
    const uint32_t smb = cvta_smem(smh);

    float acc[4][4][4];
    #pragma unroll
    for (int i = 0; i < 4; i++)
        #pragma unroll
        for (int j = 0; j < 4; j++)
            #pragma unroll
            for (int l = 0; l < 4; l++) acc[i][j][l] = 0.f;

    const int nt = K >> 5;

    auto load_stage = [&](int s, int t) {
        const int k0 = t << 5;
        uint32_t sa = smb + (uint32_t)(s * STAGE_H * 2);
        const __half* ga = A + (long)row0 * K + k0;
        #pragma unroll
        for (int i = 0; i < 2; i++) {
            int id = tid + (i << 8);
            int r = id >> 2, c = id & 3;
            cp16(sa + (uint32_t)(r * 80 + c * 16), ga + (long)r * K + (c << 3));
        }
        uint32_t sb = smb + (uint32_t)((s * STAGE_H + AT_H) * 2);
        const __half* gb = B + (long)col0 * K + k0;
        #pragma unroll
        for (int i = 0; i < 2; i++) {
            int id = tid + (i << 8);
            int r = id >> 2, c = id & 3;
            cp16(sb + (uint32_t)(r * 80 + c * 16), gb + (long)r * K + (c << 3));
        }
        cp_commit();
    };

    const int a_row = (lane & 7) + ((lane >> 3) & 1) * 8;
    const int a_kof = (lane >> 4) * 8;
    const int b_nof = (lane & 7) + ((lane >> 4) ? 8 : 0);
    const int b_kof = ((lane >> 3) & 1) * 8;

    load_stage(0, 0);
    load_stage(1, 1);

    for (int t = 0; t < nt; t++) {
        const int s = t % 3;
        if (t + 1 < nt) cp_wait<1>(); else cp_wait<0>();
        __syncthreads();
        if (t + 2 < nt) load_stage((t + 2) % 3, t + 2);

        const uint32_t sa = smb + (uint32_t)(s * STAGE_H * 2);
        const uint32_t sb = smb + (uint32_t)((s * STAGE_H + AT_H) * 2);

        #pragma unroll
        for (int ks = 0; ks < 2; ks++) {
            uint32_t af[4][4];
            #pragma unroll
            for (int ma = 0; ma < 4; ma++) {
                uint32_t ad = sa + (uint32_t)(((wm * 64 + ma * 16 + a_row) * ASTR
                                               + ks * 16 + a_kof) * 2);
                ldsm4(af[ma], ad);
            }
            uint32_t bf[4][2];
            #pragma unroll
            for (int p = 0; p < 2; p++) {
                uint32_t bd = sb + (uint32_t)(((wn * 32 + p * 16 + b_nof) * ASTR
                                               + ks * 16 + b_kof) * 2);
                ldsm4(&bf[2 * p][0], bd);
            }
            #pragma unroll
            for (int ma = 0; ma < 4; ma++)
                #pragma unroll
                for (int na = 0; na < 4; na++)
                    mma_fp16(acc[ma][na], af[ma], bf[na]);
        }
        __syncthreads();
    }

    // Epilogue
    float km = DIST ? k2m[blockIdx.z] : 0.f;
    #pragma unroll
    for (int ma = 0; ma < 4; ma++) {
        int r = row0 + wm * 64 + ma * 16 + (lane >> 2);
        float q2v0 = 0.f, q2v1 = 0.f, cr0 = 0.f, cr1 = 0.f;
        if (DIST) {
            q2v0 = q2p[r]; q2v1 = q2p[r + 8];
            cr0 = sqrtf(q2v0 + km); cr1 = sqrtf(q2v1 + km);
        }
        #pragma unroll
        for (int na = 0; na < 4; na++) {
            int cc = col0 + wn * 32 + na * 8 + 2 * (lane & 3);
            float c0 = acc[ma][na][0], c1 = acc[ma][na][1];
            float c2 = acc[ma][na][2], c3 = acc[ma][na][3];
            if (DIST) {
                float k2v0 = k2p[cc], k2v1 = k2p[cc + 1];
                c0 = sqrtf(fmaxf(q2v0 + k2v0 - 2.f * c0, 0.f)) - cr0;
                c1 = sqrtf(fmaxf(q2v0 + k2v1 - 2.f * c1, 0.f)) - cr0;
                c2 = sqrtf(fmaxf(q2v1 + k2v0 - 2.f * c2, 0.f)) - cr1;
                c3 = sqrtf(fmaxf(q2v1 + k2v1 - 2.f * c3, 0.f)) - cr1;
            }
            if (RELU) {
                c0 = fmaxf(c0, 0.f); c1 = fmaxf(c1, 0.f);
                c2 = fmaxf(c2, 0.f); c3 = fmaxf(c3, 0.f);
            }
            if (sizeof(TOUT) == 2) {
                *(__half2*)((__half*)C + (long)r * Nc + cc) =
                    __floats2half2_rn(c0, c1);
                *(__half2*)((__half*)C + (long)(r + 8) * Nc + cc) =
                    __floats2half2_rn(c2, c3);
            } else {
                *(float2*)((float*)C + (long)r * Nc + cc) = make_float2(c0, c1);
                *(float2*)((float*)C + (long)(r + 8) * Nc + cc) = make_float2(c2, c3);
            }
        }
    }
}

// ---------------------------------------------------------------------------
// Conversion / transpose kernels
// ---------------------------------------------------------------------------
__global__ __launch_bounds__(256) void conv_f2h(
    const float* __restrict__ in, __half* __restrict__ out)
{
    long i = ((long)blockIdx.x * 256 + threadIdx.x) * 4;
    float4 v = *(const float4*)(in + i);
    *(__half2*)(out + i)     = __floats2half2_rn(v.x, v.y);
    *(__half2*)(out + i + 2) = __floats2half2_rn(v.z, v.w);
}

// x -> xh, and also into the left half of h = [x | ln1] (fp16)
__global__ __launch_bounds__(256) void conv_x_pack(
    const float* __restrict__ in, __half* __restrict__ xh,
    __half* __restrict__ hh)
{
    long i = ((long)blockIdx.x * 256 + threadIdx.x) * 4;
    float4 v = *(const float4*)(in + i);
    __half2 h0 = __floats2half2_rn(v.x, v.y);
    __half2 h1 = __floats2half2_rn(v.z, v.w);
    *(__half2*)(xh + i) = h0;
    *(__half2*)(xh + i + 2) = h1;
    long row = i >> 9;          // /512
    int col = (int)(i & 511);
    __half* hr = hh + row * (2 * DD) + col;
    *(__half2*)hr = h0;
    *(__half2*)(hr + 2) = h1;
}

__global__ void trans_f2h(const float* __restrict__ in, __half* __restrict__ out,
                          int R, int C)
{
    __shared__ float t[32][33];
    int c0 = blockIdx.x * 32, r0 = blockIdx.y * 32;
    #pragma unroll
    for (int i = threadIdx.y; i < 32; i += 8)
        t[i][threadIdx.x] = in[(long)(r0 + i) * C + c0 + threadIdx.x];
    __syncthreads();
    #pragma unroll
    for (int i = threadIdx.y; i < 32; i += 8)
        out[(long)(c0 + i) * R + r0 + threadIdx.x] = __float2half_rn(t[threadIdx.x][i]);
}

__global__ void trans_h2h(const __half* __restrict__ in, __half* __restrict__ out,
                          int R, int C)
{
    __shared__ __half t[32][33];
    long bi = (long)blockIdx.z * R * C;
    int c0 = blockIdx.x * 32, r0 = blockIdx.y * 32;
    #pragma unroll
    for (int i = threadIdx.y; i < 32; i += 8)
        t[i][threadIdx.x] = in[bi + (long)(r0 + i) * C + c0 + threadIdx.x];
    __syncthreads();
    #pragma unroll
    for (int i = threadIdx.y; i < 32; i += 8)
        out[bi + (long)(c0 + i) * R + r0 + threadIdx.x] = t[threadIdx.x][i];
}

// ---------------------------------------------------------------------------
// Reductions
// ---------------------------------------------------------------------------
__device__ __forceinline__ float warpSum(float v) {
    #pragma unroll
    for (int o = 16; o > 0; o >>= 1) v += __shfl_xor_sync(0xffffffffu, v, o);
    return v;
}
__device__ __forceinline__ float warpMax(float v) {
    #pragma unroll
    for (int o = 16; o > 0; o >>= 1) v = fmaxf(v, __shfl_xor_sync(0xffffffffu, v, o));
    return v;
}
__device__ float blockSum(float v) {
    __shared__ float sh[8];
    __shared__ float tot;
    __syncthreads();
    int lane = threadIdx.x & 31, w = threadIdx.x >> 5;
    v = warpSum(v);
    if (lane == 0) sh[w] = v;
    __syncthreads();
    if (w == 0) {
        float t = (threadIdx.x < (blockDim.x >> 5)) ? sh[threadIdx.x] : 0.f;
        t = warpSum(t);
        if (threadIdx.x == 0) tot = t;
    }
    __syncthreads();
    return tot;
}
__device__ float blockMax(float v) {
    __shared__ float sh[8];
    __shared__ float tot;
    __syncthreads();
    int lane = threadIdx.x & 31, w = threadIdx.x >> 5;
    v = warpMax(v);
    if (lane == 0) sh[w] = v;
    __syncthreads();
    if (w == 0) {
        float t = (threadIdx.x < (blockDim.x >> 5)) ? sh[threadIdx.x] : -INFINITY;
        t = warpMax(t);
        if (threadIdx.x == 0) tot = t;
    }
    __syncthreads();
    return tot;
}

// ---------------------------------------------------------------------------
// Elementwise kernels
// ---------------------------------------------------------------------------
__global__ __launch_bounds__(256) void rownorm_h(
    const __half* __restrict__ X, float* __restrict__ out)
{
    const __half2* x = (const __half2*)(X + (long)blockIdx.x * DD);
    float2 f = __half22float2(x[threadIdx.x]);
    float s = blockSum(f.x * f.x + f.y * f.y);
    if (threadIdx.x == 0) out[blockIdx.x] = s;
}

// per-batch mean of k2
__global__ __launch_bounds__(256) void k2mean_k(
    const float* __restrict__ k2, float* __restrict__ k2m)
{
    const float* kk = k2 + (long)blockIdx.x * SK;
    float s = 0.f;
    #pragma unroll
    for (int i = 0; i < SK / 256; i++) s += kk[threadIdx.x + i * 256];
    s = blockSum(s);
    if (threadIdx.x == 0) k2m[blockIdx.x] = s * (1.f / SK);
}

// softmax over fp16 shifted-dist row (in place)
__global__ __launch_bounds__(256) void softmax_k(__half* __restrict__ dist)
{
    __half2* row = (__half2*)(dist + (long)blockIdx.x * SK);

    float d[16];
    float mx = -INFINITY;
    #pragma unroll
    for (int i = 0; i < 8; i++) {
        int j = threadIdx.x + i * 256;
        float2 f = __half22float2(row[j]);
        d[2 * i] = f.x; d[2 * i + 1] = f.y;
        mx = fmaxf(mx, fmaxf(f.x, f.y));
    }
    mx = blockMax(mx);

    float s = 0.f;
    #pragma unroll
    for (int i = 0; i < 16; i++) {
        d[i] = expf(d[i] - mx);
        s += d[i];
    }
    s = blockSum(s);
    float inv = 1.f / s;
    #pragma unroll
    for (int i = 0; i < 8; i++) {
        int j = threadIdx.x + i * 256;
        row[j] = __floats2half2_rn(d[2 * i] * inv, d[2 * i + 1] * inv);
    }
}

// LayerNorm(mm) -> right half of h (left half pre-filled by conv_x_pack)
__global__ __launch_bounds__(256) void ln1_pack_k(
    const float* __restrict__ mm,
    const float* __restrict__ g, const float* __restrict__ b,
    __half* __restrict__ h)
{
    const int row = blockIdx.x;
    const float* m = mm + (long)row * DD;
    const int c0 = threadIdx.x, c1 = threadIdx.x + 256;
    float v0 = m[c0], v1 = m[c1];
    float mean = blockSum(v0 + v1) * (1.f / DD);
    float var  = blockSum(v0 * v0 + v1 * v1) * (1.f / DD) - mean * mean;
    float inv = rsqrtf(var + LN_EPS);

    __half* hr = h + (long)row * (2 * DD);
    hr[DD + c0] = __float2half_rn((v0 - mean) * inv * g[c0] + b[c0]);
    hr[DD + c1] = __float2half_rn((v1 - mean) * inv * g[c1] + b[c1]);
}

__global__ __launch_bounds__(256) void ln2_add_k(
    const float* __restrict__ t, const float* __restrict__ x,
    const float* __restrict__ g, const float* __restrict__ b,
    float* __restrict__ out)
{
    const int row = blockIdx.x;
    const float* tr = t + (long)row * DD;
    const int c0 = threadIdx.x, c1 = threadIdx.x + 256;
    float v0 = tr[c0], v1 = tr[c1];
    float mean = blockSum(v0 + v1) * (1.f / DD);
    float var  = blockSum(v0 * v0 + v1 * v1) * (1.f / DD) - mean * mean;
    float inv = rsqrtf(var + LN_EPS);

    const float* xr = x + (long)row * DD;
    float* orow = out + (long)row * DD;
    orow[c0] = xr[c0] + (v0 - mean) * inv * g[c0] + b[c0];
    orow[c1] = xr[c1] + (v1 - mean) * inv * g[c1] + b[c1];
}

// ---------------------------------------------------------------------------
// Launch
// ---------------------------------------------------------------------------
extern "C" void kernel_launch(void* const* d_in, const int* in_sizes, int n_in,
                              void* d_out, int out_size)
{
    const float* x   = (const float*)d_in[0];
    const float* src = (const float*)d_in[1];
    const float* Wq  = (const float*)d_in[2];
    const float* Wk  = (const float*)d_in[3];
    const float* Wv  = (const float*)d_in[4];
    const float* Wm  = (const float*)d_in[5];
    const float* W1  = (const float*)d_in[6];
    const float* W2  = (const float*)d_in[7];
    const float* g1  = (const float*)d_in[8];
    const float* b1  = (const float*)d_in[9];
    const float* g2  = (const float*)d_in[10];
    const float* b2  = (const float*)d_in[11];
    float* out = (float*)d_out;

    __half *xh, *srch, *qh, *kh, *vh, *vt, *sch, *msgh, *hh, *fc1h;
    __half *wqt, *wkt, *wvt, *wmt, *w1t, *w2t;
    float *tmp, *q2, *k2, *k2m;
    cudaGetSymbolAddress((void**)&xh,   g_xh);
    cudaGetSymbolAddress((void**)&srch, g_srch);
    cudaGetSymbolAddress((void**)&qh,   g_qh);
    cudaGetSymbolAddress((void**)&kh,   g_kh);
    cudaGetSymbolAddress((void**)&vh,   g_vh);
    cudaGetSymbolAddress((void**)&vt,   g_vt);
    cudaGetSymbolAddress((void**)&sch,  g_sch);
    cudaGetSymbolAddress((void**)&msgh, g_msgh);
    cudaGetSymbolAddress((void**)&hh,   g_hh);
    cudaGetSymbolAddress((void**)&fc1h, g_fc1h);
    cudaGetSymbolAddress((void**)&wqt,  g_wqt);
    cudaGetSymbolAddress((void**)&wkt,  g_wkt);
    cudaGetSymbolAddress((void**)&wvt,  g_wvt);
    cudaGetSymbolAddress((void**)&wmt,  g_wmt);
    cudaGetSymbolAddress((void**)&w1t,  g_w1t);
    cudaGetSymbolAddress((void**)&w2t,  g_w2t);
    cudaGetSymbolAddress((void**)&tmp,  g_tmp);
    cudaGetSymbolAddress((void**)&q2,   g_q2);
    cudaGetSymbolAddress((void**)&k2,   g_k2);
    cudaGetSymbolAddress((void**)&k2m,  g_k2m);

    cudaFuncSetAttribute((const void*)hgemm<false, __half, false>,
        cudaFuncAttributeMaxDynamicSharedMemorySize, SMEM_GEMM);
    cudaFuncSetAttribute((const void*)hgemm<false, float, false>,
        cudaFuncAttributeMaxDynamicSharedMemorySize, SMEM_GEMM);
    cudaFuncSetAttribute((const void*)hgemm<true, __half, false>,
        cudaFuncAttributeMaxDynamicSharedMemorySize, SMEM_GEMM);
    cudaFuncSetAttribute((const void*)hgemm<false, __half, true>,
        cudaFuncAttributeMaxDynamicSharedMemorySize, SMEM_GEMM);

    dim3 t32(32, 8, 1);

    // Conversions / transposes
    conv_f2h<<<(MKV * DD) / 1024, 256>>>(src, srch);
    conv_x_pack<<<(MQ * DD) / 1024, 256>>>(x, xh, hh);
    trans_f2h<<<dim3(DD / 32, DD / 32), t32>>>(Wk, wkt, DD, DD);
    // k projection
    hgemm<false, __half, false><<<dim3(DD / 128, MKV / 128, 1), 256, SMEM_GEMM>>>(
        srch, wkt, kh, MKV, DD, DD, 0, 0, 0, nullptr, nullptr, nullptr);
    trans_f2h<<<dim3(DD / 32, DD / 32), t32>>>(Wq, wqt, DD, DD);
    // q projection
    hgemm<false, __half, false><<<dim3(DD / 128, MQ / 128, 1), 256, SMEM_GEMM>>>(
        xh, wqt, qh, MQ, DD, DD, 0, 0, 0, nullptr, nullptr, nullptr);
    trans_f2h<<<dim3(DD / 32, DD / 32), t32>>>(Wv, wvt, DD, DD);
    // v projection
    hgemm<false, __half, false><<<dim3(DD / 128, MKV / 128, 1), 256, SMEM_GEMM>>>(
        srch, wvt, vh, MKV, DD, DD, 0, 0, 0, nullptr, nullptr, nullptr);

    // Row squared norms (of the quantized fp16 values the MMAs consume)
    rownorm_h<<<MQ, 256>>>(qh, q2);
    rownorm_h<<<MKV, 256>>>(kh, k2);
    k2mean_k<<<NB, 256>>>(k2, k2m);

    // Remaining weight transposes
    trans_f2h<<<dim3(DD / 32, DD / 32), t32>>>(Wm, wmt, DD, DD);
    trans_f2h<<<dim3(2 * DD / 32, 2 * DD / 32), t32>>>(W1, w1t, 2 * DD, 2 * DD);
    trans_f2h<<<dim3(DD / 32, 2 * DD / 32), t32>>>(W2, w2t, 2 * DD, DD);

    // v transpose per batch: [S,D] -> [D,S]
    trans_h2h<<<dim3(DD / 32, SK / 32, NB), t32>>>(vh, vt, SK, DD);

    // Shifted dist fused into scores GEMM (fp16 out)
    hgemm<false, __half, true><<<dim3(SK / 128, LQ / 128, NB), 256, SMEM_GEMM>>>(
        qh, kh, sch, LQ, SK, DD,
        (long)LQ * DD, (long)SK * DD, (long)LQ * SK, q2, k2, k2m);

    // softmax in place -> fp16 attn
    softmax_k<<<MQ, 256>>>(sch);

    // message = attn @ v  (NT with vt, fp16 out)
    hgemm<false, __half, false><<<dim3(DD / 128, LQ / 128, NB), 256, SMEM_GEMM>>>(
        sch, vt, msgh, LQ, DD, SK,
        (long)LQ * SK, (long)DD * SK, (long)LQ * DD, nullptr, nullptr, nullptr);

    // mm = message @ Wm (fp32 out)
    hgemm<false, float, false><<<dim3(DD / 128, MQ / 128, 1), 256, SMEM_GEMM>>>(
        msgh, wmt, tmp, MQ, DD, DD, 0, 0, 0, nullptr, nullptr, nullptr);

    // h right half = LayerNorm(mm)
    ln1_pack_k<<<MQ, 256>>>(tmp, g1, b1, hh);

    // fc1 = relu(h @ W1) (fp16 out)
    hgemm<true, __half, false><<<dim3(2 * DD / 128, MQ / 128, 1), 256, SMEM_GEMM>>>(
        hh, w1t, fc1h, MQ, 2 * DD, 2 * DD, 0, 0, 0, nullptr, nullptr, nullptr);

    // fc2 = fc1 @ W2 (fp32 out)
    hgemm<false, float, false><<<dim3(DD / 128, MQ / 128, 1), 256, SMEM_GEMM>>>(
        fc1h, w2t, tmp, MQ, DD, 2 * DD, 0, 0, 0, nullptr, nullptr, nullptr);

    // out = x + LayerNorm(fc2)
    ln2_add_k<<<MQ, 256>>>(tmp, x, g2, b2, out);
}

// round 13
// speedup vs baseline: 1.2183x; 1.1108x over previous
#include <cuda_runtime.h>
#include <cuda_fp16.h>
#include <math.h>
#include <stdint.h>

// Problem constants
#define NB 8
#define LQ 1024
#define SK 4096
#define DD 512
#define MQ  (NB * LQ)   // 8192
#define MKV (NB * SK)   // 32768
#define LN_EPS 1e-5f

// ---------------------------------------------------------------------------
// Scratch (device globals)
// ---------------------------------------------------------------------------
__device__ __half g_xh  [(size_t)MQ  * DD];
__device__ __half g_srch[(size_t)MKV * DD];
__device__ __half g_qh  [(size_t)MQ  * DD];
__device__ __half g_kh  [(size_t)MKV * DD];
__device__ __half g_vh  [(size_t)MKV * DD];
__device__ __half g_vt  [(size_t)MKV * DD];          // per batch [D,S]
__device__ __half g_sch [(size_t)NB * LQ * SK];      // shifted dist -> attn (in place)
__device__ __half g_msgh[(size_t)MQ * DD];
__device__ __half g_hh  [(size_t)MQ * 2 * DD];
__device__ __half g_fc1h[(size_t)MQ * 2 * DD];
__device__ __half g_wqt [DD * DD];
__device__ __half g_wkt [DD * DD];
__device__ __half g_wvt [DD * DD];
__device__ __half g_wmt [DD * DD];
__device__ __half g_w1t [2 * DD * 2 * DD];
__device__ __half g_w2t [DD * 2 * DD];
__device__ float  g_tmp [(size_t)MQ * DD];
__device__ float  g_q2  [MQ];
__device__ float  g_k2  [MKV];
__device__ float  g_k2m [NB];

// ---------------------------------------------------------------------------
// PTX helpers (base compute_103 only)
// ---------------------------------------------------------------------------
__device__ __forceinline__ uint32_t cvta_smem(const void* p) {
    uint32_t a;
    asm("{ .reg .u64 t; cvta.to.shared.u64 t, %1; cvt.u32.u64 %0, t; }"
        : "=r"(a) : "l"(p));
    return a;
}
__device__ __forceinline__ void cp16(uint32_t d, const void* s) {
    asm volatile("cp.async.cg.shared.global [%0], [%1], 16;"
                 :: "r"(d), "l"(s));
}
__device__ __forceinline__ void cp_commit() {
    asm volatile("cp.async.commit_group;" ::: "memory");
}
template <int N>
__device__ __forceinline__ void cp_wait() {
    asm volatile("cp.async.wait_group %0;" :: "n"(N) : "memory");
}
__device__ __forceinline__ void ldsm4(uint32_t* r, uint32_t addr) {
    asm volatile("ldmatrix.sync.aligned.m8n8.x4.shared.b16 {%0,%1,%2,%3}, [%4];"
        : "=r"(r[0]), "=r"(r[1]), "=r"(r[2]), "=r"(r[3]) : "r"(addr));
}
__device__ __forceinline__ void mma_fp16(float* c, const uint32_t* a,
                                         const uint32_t* b) {
    asm volatile(
        "mma.sync.aligned.m16n8k16.row.col.f32.f16.f16.f32 "
        "{%0,%1,%2,%3}, {%4,%5,%6,%7}, {%8,%9}, {%0,%1,%2,%3};"
        : "+f"(c[0]), "+f"(c[1]), "+f"(c[2]), "+f"(c[3])
        : "r"(a[0]), "r"(a[1]), "r"(a[2]), "r"(a[3]),
          "r"(b[0]), "r"(b[1]));
}

// ---------------------------------------------------------------------------
// fp16 NT GEMM: C[M,Nc] = A[M,K] @ B[Nc,K]^T   (fp32 accumulate)
// Block tile 128x128x64, 8 warps (2x4) of 64x32 warp tiles, 2-stage cp.async
// double buffer with ONE __syncthreads per k-iter, ldmatrix.x4 fragment loads,
// 2 CTAs per SM. M%128==0, Nc%128==0, K%64==0.
// DIST: C = sqrt(max(q2[r]+k2[c]-2acc,0)) - sqrt(q2[r]+k2m[z])  (fp16 store)
// ---------------------------------------------------------------------------
constexpr int ASTR = 72;                 // halfs per smem row (64 + 8 pad)
constexpr int AT_H = 128 * ASTR;         // 9216 halfs
constexpr int BT_H = 128 * ASTR;         // 9216 halfs
constexpr int STAGE_H = AT_H + BT_H;     // 18432 halfs = 36864 B
#define SMEM_GEMM (2 * STAGE_H * 2)      // 73728 B per CTA (2 CTAs = 147KB/SM)

template <bool RELU, typename TOUT, bool DIST>
__global__ __launch_bounds__(256, 2) void hgemm(
    const __half* __restrict__ A, const __half* __restrict__ B,
    TOUT* __restrict__ C, int M, int Nc, int K,
    long sA, long sB, long sC,
    const float* __restrict__ q2, const float* __restrict__ k2,
    const float* __restrict__ k2m)
{
    extern __shared__ __align__(16) __half smh[];
    A += (long)blockIdx.z * sA;
    B += (long)blockIdx.z * sB;
    C += (long)blockIdx.z * sC;
    const float* q2p = DIST ? q2 + (long)blockIdx.z * LQ : nullptr;
    const float* k2p = DIST ? k2 + (long)blockIdx.z * SK : nullptr;

    const int tid = threadIdx.x, lane = tid & 31, wid = tid >> 5;
    const int wm = wid >> 2, wn = wid & 3;       // 2 x 4 warp grid
    const int row0 = blockIdx.y * 128, col0 = blockIdx.x * 128;
    const uint32_t smb = cvta_smem(smh);

    float acc[4][4][4];
    #pragma unroll
    for (int i = 0; i < 4; i++)
        #pragma unroll
        for (int j = 0; j < 4; j++)
            #pragma unroll
            for (int l = 0; l < 4; l++) acc[i][j][l] = 0.f;

    const int nt = K >> 6;   // 64-wide k-iters

    // Stage load: A 128 rows x 8 16B-chunks + B 128 rows x 8 chunks
    // = 2048 cp16, 8 per thread.
    auto load_stage = [&](int s, int t) {
        const int k0 = t << 6;
        uint32_t sa = smb + (uint32_t)(s * STAGE_H * 2);
        const __half* ga = A + (long)row0 * K + k0;
        #pragma unroll
        for (int i = 0; i < 4; i++) {
            int id = tid + (i << 8);
            int r = id >> 3, c = id & 7;
            cp16(sa + (uint32_t)(r * 144 + c * 16), ga + (long)r * K + (c << 3));
        }
        uint32_t sb = smb + (uint32_t)((s * STAGE_H + AT_H) * 2);
        const __half* gb = B + (long)col0 * K + k0;
        #pragma unroll
        for (int i = 0; i < 4; i++) {
            int id = tid + (i << 8);
            int r = id >> 3, c = id & 7;
            cp16(sb + (uint32_t)(r * 144 + c * 16), gb + (long)r * K + (c << 3));
        }
        cp_commit();
    };

    const int a_row = (lane & 7) + ((lane >> 3) & 1) * 8;
    const int a_kof = (lane >> 4) * 8;
    const int b_nof = (lane & 7) + ((lane >> 4) ? 8 : 0);
    const int b_kof = ((lane >> 3) & 1) * 8;

    load_stage(0, 0);

    for (int t = 0; t < nt; t++) {
        const int s = t & 1;
        cp_wait<0>();          // own groups done (only load(t) outstanding)
        __syncthreads();       // all warps' loads visible; prior reads closed
        if (t + 1 < nt) load_stage(s ^ 1, t + 1);   // overlaps compute below

        const uint32_t sa = smb + (uint32_t)(s * STAGE_H * 2);
        const uint32_t sb = smb + (uint32_t)((s * STAGE_H + AT_H) * 2);

        #pragma unroll
        for (int ks = 0; ks < 4; ks++) {
            uint32_t af[4][4];
            #pragma unroll
            for (int ma = 0; ma < 4; ma++) {
                uint32_t ad = sa + (uint32_t)(((wm * 64 + ma * 16 + a_row) * ASTR
                                               + ks * 16 + a_kof) * 2);
                ldsm4(af[ma], ad);
            }
            uint32_t bf[4][2];
            #pragma unroll
            for (int p = 0; p < 2; p++) {
                uint32_t bd = sb + (uint32_t)(((wn * 32 + p * 16 + b_nof) * ASTR
                                               + ks * 16 + b_kof) * 2);
                ldsm4(&bf[2 * p][0], bd);
            }
            #pragma unroll
            for (int ma = 0; ma < 4; ma++)
                #pragma unroll
                for (int na = 0; na < 4; na++)
                    mma_fp16(acc[ma][na], af[ma], bf[na]);
        }
    }

    // Epilogue
    float km = DIST ? k2m[blockIdx.z] : 0.f;
    #pragma unroll
    for (int ma = 0; ma < 4; ma++) {
        int r = row0 + wm * 64 + ma * 16 + (lane >> 2);
        float q2v0 = 0.f, q2v1 = 0.f, cr0 = 0.f, cr1 = 0.f;
        if (DIST) {
            q2v0 = q2p[r]; q2v1 = q2p[r + 8];
            cr0 = sqrtf(q2v0 + km); cr1 = sqrtf(q2v1 + km);
        }
        #pragma unroll
        for (int na = 0; na < 4; na++) {
            int cc = col0 + wn * 32 + na * 8 + 2 * (lane & 3);
            float c0 = acc[ma][na][0], c1 = acc[ma][na][1];
            float c2 = acc[ma][na][2], c3 = acc[ma][na][3];
            if (DIST) {
                float k2v0 = k2p[cc], k2v1 = k2p[cc + 1];
                c0 = sqrtf(fmaxf(q2v0 + k2v0 - 2.f * c0, 0.f)) - cr0;
                c1 = sqrtf(fmaxf(q2v0 + k2v1 - 2.f * c1, 0.f)) - cr0;
                c2 = sqrtf(fmaxf(q2v1 + k2v0 - 2.f * c2, 0.f)) - cr1;
                c3 = sqrtf(fmaxf(q2v1 + k2v1 - 2.f * c3, 0.f)) - cr1;
            }
            if (RELU) {
                c0 = fmaxf(c0, 0.f); c1 = fmaxf(c1, 0.f);
                c2 = fmaxf(c2, 0.f); c3 = fmaxf(c3, 0.f);
            }
            if (sizeof(TOUT) == 2) {
                *(__half2*)((__half*)C + (long)r * Nc + cc) =
                    __floats2half2_rn(c0, c1);
                *(__half2*)((__half*)C + (long)(r + 8) * Nc + cc) =
                    __floats2half2_rn(c2, c3);
            } else {
                *(float2*)((float*)C + (long)r * Nc + cc) = make_float2(c0, c1);
                *(float2*)((float*)C + (long)(r + 8) * Nc + cc) = make_float2(c2, c3);
            }
        }
    }
}

// ---------------------------------------------------------------------------
// Conversion / transpose kernels
// ---------------------------------------------------------------------------
__global__ __launch_bounds__(256) void conv_f2h(
    const float* __restrict__ in, __half* __restrict__ out)
{
    long i = ((long)blockIdx.x * 256 + threadIdx.x) * 4;
    float4 v = *(const float4*)(in + i);
    *(__half2*)(out + i)     = __floats2half2_rn(v.x, v.y);
    *(__half2*)(out + i + 2) = __floats2half2_rn(v.z, v.w);
}

// x -> xh, and also into the left half of h = [x | ln1] (fp16)
__global__ __launch_bounds__(256) void conv_x_pack(
    const float* __restrict__ in, __half* __restrict__ xh,
    __half* __restrict__ hh)
{
    long i = ((long)blockIdx.x * 256 + threadIdx.x) * 4;
    float4 v = *(const float4*)(in + i);
    __half2 h0 = __floats2half2_rn(v.x, v.y);
    __half2 h1 = __floats2half2_rn(v.z, v.w);
    *(__half2*)(xh + i) = h0;
    *(__half2*)(xh + i + 2) = h1;
    long row = i >> 9;          // /512
    int col = (int)(i & 511);
    __half* hr = hh + row * (2 * DD) + col;
    *(__half2*)hr = h0;
    *(__half2*)(hr + 2) = h1;
}

__global__ void trans_f2h(const float* __restrict__ in, __half* __restrict__ out,
                          int R, int C)
{
    __shared__ float t[32][33];
    int c0 = blockIdx.x * 32, r0 = blockIdx.y * 32;
    #pragma unroll
    for (int i = threadIdx.y; i < 32; i += 8)
        t[i][threadIdx.x] = in[(long)(r0 + i) * C + c0 + threadIdx.x];
    __syncthreads();
    #pragma unroll
    for (int i = threadIdx.y; i < 32; i += 8)
        out[(long)(c0 + i) * R + r0 + threadIdx.x] = __float2half_rn(t[threadIdx.x][i]);
}

__global__ void trans_h2h(const __half* __restrict__ in, __half* __restrict__ out,
                          int R, int C)
{
    __shared__ __half t[32][33];
    long bi = (long)blockIdx.z * R * C;
    int c0 = blockIdx.x * 32, r0 = blockIdx.y * 32;
    #pragma unroll
    for (int i = threadIdx.y; i < 32; i += 8)
        t[i][threadIdx.x] = in[bi + (long)(r0 + i) * C + c0 + threadIdx.x];
    __syncthreads();
    #pragma unroll
    for (int i = threadIdx.y; i < 32; i += 8)
        out[bi + (long)(c0 + i) * R + r0 + threadIdx.x] = t[threadIdx.x][i];
}

// ---------------------------------------------------------------------------
// Reductions
// ---------------------------------------------------------------------------
__device__ __forceinline__ float warpSum(float v) {
    #pragma unroll
    for (int o = 16; o > 0; o >>= 1) v += __shfl_xor_sync(0xffffffffu, v, o);
    return v;
}
__device__ __forceinline__ float warpMax(float v) {
    #pragma unroll
    for (int o = 16; o > 0; o >>= 1) v = fmaxf(v, __shfl_xor_sync(0xffffffffu, v, o));
    return v;
}
__device__ float blockSum(float v) {
    __shared__ float sh[8];
    __shared__ float tot;
    __syncthreads();
    int lane = threadIdx.x & 31, w = threadIdx.x >> 5;
    v = warpSum(v);
    if (lane == 0) sh[w] = v;
    __syncthreads();
    if (w == 0) {
        float t = (threadIdx.x < (blockDim.x >> 5)) ? sh[threadIdx.x] : 0.f;
        t = warpSum(t);
        if (threadIdx.x == 0) tot = t;
    }
    __syncthreads();
    return tot;
}
__device__ float blockMax(float v) {
    __shared__ float sh[8];
    __shared__ float tot;
    __syncthreads();
    int lane = threadIdx.x & 31, w = threadIdx.x >> 5;
    v = warpMax(v);
    if (lane == 0) sh[w] = v;
    __syncthreads();
    if (w == 0) {
        float t = (threadIdx.x < (blockDim.x >> 5)) ? sh[threadIdx.x] : -INFINITY;
        t = warpMax(t);
        if (threadIdx.x == 0) tot = t;
    }
    __syncthreads();
    return tot;
}

// ---------------------------------------------------------------------------
// Elementwise kernels
// ---------------------------------------------------------------------------
__global__ __launch_bounds__(256) void rownorm_h(
    const __half* __restrict__ X, float* __restrict__ out)
{
    const __half2* x = (const __half2*)(X + (long)blockIdx.x * DD);
    float2 f = __half22float2(x[threadIdx.x]);
    float s = blockSum(f.x * f.x + f.y * f.y);
    if (threadIdx.x == 0) out[blockIdx.x] = s;
}

// per-batch mean of k2
__global__ __launch_bounds__(256) void k2mean_k(
    const float* __restrict__ k2, float* __restrict__ k2m)
{
    const float* kk = k2 + (long)blockIdx.x * SK;
    float s = 0.f;
    #pragma unroll
    for (int i = 0; i < SK / 256; i++) s += kk[threadIdx.x + i * 256];
    s = blockSum(s);
    if (threadIdx.x == 0) k2m[blockIdx.x] = s * (1.f / SK);
}

// softmax over fp16 shifted-dist row (in place)
__global__ __launch_bounds__(256) void softmax_k(__half* __restrict__ dist)
{
    __half2* row = (__half2*)(dist + (long)blockIdx.x * SK);

    float d[16];
    float mx = -INFINITY;
    #pragma unroll
    for (int i = 0; i < 8; i++) {
        int j = threadIdx.x + i * 256;
        float2 f = __half22float2(row[j]);
        d[2 * i] = f.x; d[2 * i + 1] = f.y;
        mx = fmaxf(mx, fmaxf(f.x, f.y));
    }
    mx = blockMax(mx);

    float s = 0.f;
    #pragma unroll
    for (int i = 0; i < 16; i++) {
        d[i] = expf(d[i] - mx);
        s += d[i];
    }
    s = blockSum(s);
    float inv = 1.f / s;
    #pragma unroll
    for (int i = 0; i < 8; i++) {
        int j = threadIdx.x + i * 256;
        row[j] = __floats2half2_rn(d[2 * i] * inv, d[2 * i + 1] * inv);
    }
}

// LayerNorm(mm) -> right half of h (left half pre-filled by conv_x_pack)
__global__ __launch_bounds__(256) void ln1_pack_k(
    const float* __restrict__ mm,
    const float* __restrict__ g, const float* __restrict__ b,
    __half* __restrict__ h)
{
    const int row = blockIdx.x;
    const float* m = mm + (long)row * DD;
    const int c0 = threadIdx.x, c1 = threadIdx.x + 256;
    float v0 = m[c0], v1 = m[c1];
    float mean = blockSum(v0 + v1) * (1.f / DD);
    float var  = blockSum(v0 * v0 + v1 * v1) * (1.f / DD) - mean * mean;
    float inv = rsqrtf(var + LN_EPS);

    __half* hr = h + (long)row * (2 * DD);
    hr[DD + c0] = __float2half_rn((v0 - mean) * inv * g[c0] + b[c0]);
    hr[DD + c1] = __float2half_rn((v1 - mean) * inv * g[c1] + b[c1]);
}

__global__ __launch_bounds__(256) void ln2_add_k(
    const float* __restrict__ t, const float* __restrict__ x,
    const float* __restrict__ g, const float* __restrict__ b,
    float* __restrict__ out)
{
    const int row = blockIdx.x;
    const float* tr = t + (long)row * DD;
    const int c0 = threadIdx.x, c1 = threadIdx.x + 256;
    float v0 = tr[c0], v1 = tr[c1];
    float mean = blockSum(v0 + v1) * (1.f / DD);
    float var  = blockSum(v0 * v0 + v1 * v1) * (1.f / DD) - mean * mean;
    float inv = rsqrtf(var + LN_EPS);

    const float* xr = x + (long)row * DD;
    float* orow = out + (long)row * DD;
    orow[c0] = xr[c0] + (v0 - mean) * inv * g[c0] + b[c0];
    orow[c1] = xr[c1] + (v1 - mean) * inv * g[c1] + b[c1];
}

// ---------------------------------------------------------------------------
// Launch
// ---------------------------------------------------------------------------
extern "C" void kernel_launch(void* const* d_in, const int* in_sizes, int n_in,
                              void* d_out, int out_size)
{
    const float* x   = (const float*)d_in[0];
    const float* src = (const float*)d_in[1];
    const float* Wq  = (const float*)d_in[2];
    const float* Wk  = (const float*)d_in[3];
    const float* Wv  = (const float*)d_in[4];
    const float* Wm  = (const float*)d_in[5];
    const float* W1  = (const float*)d_in[6];
    const float* W2  = (const float*)d_in[7];
    const float* g1  = (const float*)d_in[8];
    const float* b1  = (const float*)d_in[9];
    const float* g2  = (const float*)d_in[10];
    const float* b2  = (const float*)d_in[11];
    float* out = (float*)d_out;

    __half *xh, *srch, *qh, *kh, *vh, *vt, *sch, *msgh, *hh, *fc1h;
    __half *wqt, *wkt, *wvt, *wmt, *w1t, *w2t;
    float *tmp, *q2, *k2, *k2m;
    cudaGetSymbolAddress((void**)&xh,   g_xh);
    cudaGetSymbolAddress((void**)&srch, g_srch);
    cudaGetSymbolAddress((void**)&qh,   g_qh);
    cudaGetSymbolAddress((void**)&kh,   g_kh);
    cudaGetSymbolAddress((void**)&vh,   g_vh);
    cudaGetSymbolAddress((void**)&vt,   g_vt);
    cudaGetSymbolAddress((void**)&sch,  g_sch);
    cudaGetSymbolAddress((void**)&msgh, g_msgh);
    cudaGetSymbolAddress((void**)&hh,   g_hh);
    cudaGetSymbolAddress((void**)&fc1h, g_fc1h);
    cudaGetSymbolAddress((void**)&wqt,  g_wqt);
    cudaGetSymbolAddress((void**)&wkt,  g_wkt);
    cudaGetSymbolAddress((void**)&wvt,  g_wvt);
    cudaGetSymbolAddress((void**)&wmt,  g_wmt);
    cudaGetSymbolAddress((void**)&w1t,  g_w1t);
    cudaGetSymbolAddress((void**)&w2t,  g_w2t);
    cudaGetSymbolAddress((void**)&tmp,  g_tmp);
    cudaGetSymbolAddress((void**)&q2,   g_q2);
    cudaGetSymbolAddress((void**)&k2,   g_k2);
    cudaGetSymbolAddress((void**)&k2m,  g_k2m);

    cudaFuncSetAttribute((const void*)hgemm<false, __half, false>,
        cudaFuncAttributeMaxDynamicSharedMemorySize, SMEM_GEMM);
    cudaFuncSetAttribute((const void*)hgemm<false, float, false>,
        cudaFuncAttributeMaxDynamicSharedMemorySize, SMEM_GEMM);
    cudaFuncSetAttribute((const void*)hgemm<true, __half, false>,
        cudaFuncAttributeMaxDynamicSharedMemorySize, SMEM_GEMM);
    cudaFuncSetAttribute((const void*)hgemm<false, __half, true>,
        cudaFuncAttributeMaxDynamicSharedMemorySize, SMEM_GEMM);

    dim3 t32(32, 8, 1);

    // Conversions / transposes
    conv_f2h<<<(MKV * DD) / 1024, 256>>>(src, srch);
    conv_x_pack<<<(MQ * DD) / 1024, 256>>>(x, xh, hh);
    trans_f2h<<<dim3(DD / 32, DD / 32), t32>>>(Wk, wkt, DD, DD);
    // k projection
    hgemm<false, __half, false><<<dim3(DD / 128, MKV / 128, 1), 256, SMEM_GEMM>>>(
        srch, wkt, kh, MKV, DD, DD, 0, 0, 0, nullptr, nullptr, nullptr);
    trans_f2h<<<dim3(DD / 32, DD / 32), t32>>>(Wq, wqt, DD, DD);
    // q projection
    hgemm<false, __half, false><<<dim3(DD / 128, MQ / 128, 1), 256, SMEM_GEMM>>>(
        xh, wqt, qh, MQ, DD, DD, 0, 0, 0, nullptr, nullptr, nullptr);
    trans_f2h<<<dim3(DD / 32, DD / 32), t32>>>(Wv, wvt, DD, DD);
    // v projection
    hgemm<false, __half, false><<<dim3(DD / 128, MKV / 128, 1), 256, SMEM_GEMM>>>(
        srch, wvt, vh, MKV, DD, DD, 0, 0, 0, nullptr, nullptr, nullptr);

    // Row squared norms (of the quantized fp16 values the MMAs consume)
    rownorm_h<<<MQ, 256>>>(qh, q2);
    rownorm_h<<<MKV, 256>>>(kh, k2);
    k2mean_k<<<NB, 256>>>(k2, k2m);

    // Remaining weight transposes
    trans_f2h<<<dim3(DD / 32, DD / 32), t32>>>(Wm, wmt, DD, DD);
    trans_f2h<<<dim3(2 * DD / 32, 2 * DD / 32), t32>>>(W1, w1t, 2 * DD, 2 * DD);
    trans_f2h<<<dim3(DD / 32, 2 * DD / 32), t32>>>(W2, w2t, 2 * DD, DD);

    // v transpose per batch: [S,D] -> [D,S]
    trans_h2h<<<dim3(DD / 32, SK / 32, NB), t32>>>(vh, vt, SK, DD);

    // Shifted dist fused into scores GEMM (fp16 out)
    hgemm<false, __half, true><<<dim3(SK / 128, LQ / 128, NB), 256, SMEM_GEMM>>>(
        qh, kh, sch, LQ, SK, DD,
        (long)LQ * DD, (long)SK * DD, (long)LQ * SK, q2, k2, k2m);

    // softmax in place -> fp16 attn
    softmax_k<<<MQ, 256>>>(sch);

    // message = attn @ v  (NT with vt, fp16 out)
    hgemm<false, __half, false><<<dim3(DD / 128, LQ / 128, NB), 256, SMEM_GEMM>>>(
        sch, vt, msgh, LQ, DD, SK,
        (long)LQ * SK, (long)DD * SK, (long)LQ * DD, nullptr, nullptr, nullptr);

    // mm = message @ Wm (fp32 out)
    hgemm<false, float, false><<<dim3(DD / 128, MQ / 128, 1), 256, SMEM_GEMM>>>(
        msgh, wmt, tmp, MQ, DD, DD, 0, 0, 0, nullptr, nullptr, nullptr);

    // h right half = LayerNorm(mm)
    ln1_pack_k<<<MQ, 256>>>(tmp, g1, b1, hh);

    // fc1 = relu(h @ W1) (fp16 out)
    hgemm<true, __half, false><<<dim3(2 * DD / 128, MQ / 128, 1), 256, SMEM_GEMM>>>(
        hh, w1t, fc1h, MQ, 2 * DD, 2 * DD, 0, 0, 0, nullptr, nullptr, nullptr);

    // fc2 = fc1 @ W2 (fp32 out)
    hgemm<false, float, false><<<dim3(DD / 128, MQ / 128, 1), 256, SMEM_GEMM>>>(
        fc1h, w2t, tmp, MQ, DD, 2 * DD, 0, 0, 0, nullptr, nullptr, nullptr);

    // out = x + LayerNorm(fc2)
    ln2_add_k<<<MQ, 256>>>(tmp, x, g2, b2, out);
}

// round 14
// speedup vs baseline: 1.2456x; 1.0224x over previous
#include <cuda_runtime.h>
#include <cuda_fp16.h>
#include <math.h>
#include <stdint.h>

// Problem constants
#define NB 8
#define LQ 1024
#define SK 4096
#define DD 512
#define MQ  (NB * LQ)   // 8192
#define MKV (NB * SK)   // 32768
#define LN_EPS 1e-5f

// ---------------------------------------------------------------------------
// Scratch (device globals)
// ---------------------------------------------------------------------------
__device__ __half g_xh  [(size_t)MQ  * DD];
__device__ __half g_srch[(size_t)MKV * DD];
__device__ __half g_qh  [(size_t)MQ  * DD];
__device__ __half g_kh  [(size_t)MKV * DD];
__device__ __half g_vh  [(size_t)MKV * DD];
__device__ __half g_vt  [(size_t)MKV * DD];          // per batch [D,S]
__device__ __half g_sch [(size_t)NB * LQ * SK];      // shifted dist -> attn (in place)
__device__ __half g_msgh[(size_t)MQ * DD];
__device__ __half g_hh  [(size_t)MQ * 2 * DD];
__device__ __half g_fc1h[(size_t)MQ * 2 * DD];
__device__ __half g_wqt [DD * DD];
__device__ __half g_wkt [DD * DD];
__device__ __half g_wvt [DD * DD];
__device__ __half g_wmt [DD * DD];
__device__ __half g_w1t [2 * DD * 2 * DD];
__device__ __half g_w2t [DD * 2 * DD];
__device__ float  g_tmp [(size_t)MQ * DD];
__device__ float  g_q2  [MQ];
__device__ float  g_k2  [MKV];
__device__ float  g_k2m [NB];

// ---------------------------------------------------------------------------
// PTX helpers (base compute_103 only)
// ---------------------------------------------------------------------------
__device__ __forceinline__ uint32_t cvta_smem(const void* p) {
    uint32_t a;
    asm("{ .reg .u64 t; cvta.to.shared.u64 t, %1; cvt.u32.u64 %0, t; }"
        : "=r"(a) : "l"(p));
    return a;
}
__device__ __forceinline__ void cp16(uint32_t d, const void* s) {
    asm volatile("cp.async.cg.shared.global [%0], [%1], 16;"
                 :: "r"(d), "l"(s));
}
__device__ __forceinline__ void cp_commit() {
    asm volatile("cp.async.commit_group;" ::: "memory");
}
template <int N>
__device__ __forceinline__ void cp_wait() {
    asm volatile("cp.async.wait_group %0;" :: "n"(N) : "memory");
}
__device__ __forceinline__ void ldsm4(uint32_t* r, uint32_t addr) {
    asm volatile("ldmatrix.sync.aligned.m8n8.x4.shared.b16 {%0,%1,%2,%3}, [%4];"
        : "=r"(r[0]), "=r"(r[1]), "=r"(r[2]), "=r"(r[3]) : "r"(addr));
}
__device__ __forceinline__ void mma_fp16(float* c, const uint32_t* a,
                                         const uint32_t* b) {
    asm volatile(
        "mma.sync.aligned.m16n8k16.row.col.f32.f16.f16.f32 "
        "{%0,%1,%2,%3}, {%4,%5,%6,%7}, {%8,%9}, {%0,%1,%2,%3};"
        : "+f"(c[0]), "+f"(c[1]), "+f"(c[2]), "+f"(c[3])
        : "r"(a[0]), "r"(a[1]), "r"(a[2]), "r"(a[3]),
          "r"(b[0]), "r"(b[1]));
}

// ---------------------------------------------------------------------------
// fp16 NT GEMM: C[M,Nc] = A[M,K] @ B[Nc,K]^T   (fp32 accumulate)
// Block tile 128x128x64, 8 warps (2x4) of 64x32 warp tiles, 3-stage cp.async
// with ONE __syncthreads per k-iter, ldmatrix.x4 fragment loads, 2 CTAs/SM.
// M%128==0, Nc%128==0, K%64==0.
// DIST: C = sqrt(max(q2[r]+k2[c]-2acc,0)) - sqrt(q2[r]+k2m[z])  (fp16 store)
// ---------------------------------------------------------------------------
constexpr int ASTR = 72;                 // halfs per smem row (64 + 8 pad)
constexpr int AT_H = 128 * ASTR;         // 9216 halfs
constexpr int BT_H = 128 * ASTR;         // 9216 halfs
constexpr int STAGE_H = AT_H + BT_H;     // 18432 halfs = 36864 B
#define SMEM_GEMM (3 * STAGE_H * 2)      // 110592 B per CTA (2 CTAs = 221KB/SM)

template <bool RELU, typename TOUT, bool DIST>
__global__ __launch_bounds__(256, 2) void hgemm(
    const __half* __restrict__ A, const __half* __restrict__ B,
    TOUT* __restrict__ C, int M, int Nc, int K,
    long sA, long sB, long sC,
    const float* __restrict__ q2, const float* __restrict__ k2,
    const float* __restrict__ k2m)
{
    extern __shared__ __align__(16) __half smh[];
    A += (long)blockIdx.z * sA;
    B += (long)blockIdx.z * sB;
    C += (long)blockIdx.z * sC;
    const float* q2p = DIST ? q2 + (long)blockIdx.z * LQ : nullptr;
    const float* k2p = DIST ? k2 + (long)blockIdx.z * SK : nullptr;

    const int tid = threadIdx.x, lane = tid & 31, wid = tid >> 5;
    const int wm = wid >> 2, wn = wid & 3;       // 2 x 4 warp grid
    const int row0 = blockIdx.y * 128, col0 = blockIdx.x * 128;
    const uint32_t smb = cvta_smem(smh);

    float acc[4][4][4];
    #pragma unroll
    for (int i = 0; i < 4; i++)
        #pragma unroll
        for (int j = 0; j < 4; j++)
            #pragma unroll
            for (int l = 0; l < 4; l++) acc[i][j][l] = 0.f;

    const int nt = K >> 6;   // 64-wide k-iters

    auto load_stage = [&](int s, int t) {
        const int k0 = t << 6;
        uint32_t sa = smb + (uint32_t)(s * STAGE_H * 2);
        const __half* ga = A + (long)row0 * K + k0;
        #pragma unroll
        for (int i = 0; i < 4; i++) {
            int id = tid + (i << 8);
            int r = id >> 3, c = id & 7;
            cp16(sa + (uint32_t)(r * 144 + c * 16), ga + (long)r * K + (c << 3));
        }
        uint32_t sb = smb + (uint32_t)((s * STAGE_H + AT_H) * 2);
        const __half* gb = B + (long)col0 * K + k0;
        #pragma unroll
        for (int i = 0; i < 4; i++) {
            int id = tid + (i << 8);
            int r = id >> 3, c = id & 7;
            cp16(sb + (uint32_t)(r * 144 + c * 16), gb + (long)r * K + (c << 3));
        }
        cp_commit();
    };

    const int a_row = (lane & 7) + ((lane >> 3) & 1) * 8;
    const int a_kof = (lane >> 4) * 8;
    const int b_nof = (lane & 7) + ((lane >> 4) ? 8 : 0);
    const int b_kof = ((lane >> 3) & 1) * 8;

    load_stage(0, 0);
    if (nt > 1) load_stage(1, 1);

    for (int t = 0; t < nt; t++) {
        const int s = t % 3;
        if (t + 1 < nt) cp_wait<1>(); else cp_wait<0>();
        __syncthreads();       // all warps' loads visible; prior reads closed
        if (t + 2 < nt) load_stage((t + 2) % 3, t + 2);   // overlaps compute

        const uint32_t sa = smb + (uint32_t)(s * STAGE_H * 2);
        const uint32_t sb = smb + (uint32_t)((s * STAGE_H + AT_H) * 2);

        #pragma unroll
        for (int ks = 0; ks < 4; ks++) {
            uint32_t af[4][4];
            #pragma unroll
            for (int ma = 0; ma < 4; ma++) {
                uint32_t ad = sa + (uint32_t)(((wm * 64 + ma * 16 + a_row) * ASTR
                                               + ks * 16 + a_kof) * 2);
                ldsm4(af[ma], ad);
            }
            uint32_t bf[4][2];
            #pragma unroll
            for (int p = 0; p < 2; p++) {
                uint32_t bd = sb + (uint32_t)(((wn * 32 + p * 16 + b_nof) * ASTR
                                               + ks * 16 + b_kof) * 2);
                ldsm4(&bf[2 * p][0], bd);
            }
            #pragma unroll
            for (int ma = 0; ma < 4; ma++)
                #pragma unroll
                for (int na = 0; na < 4; na++)
                    mma_fp16(acc[ma][na], af[ma], bf[na]);
        }
    }

    // Epilogue
    float km = DIST ? k2m[blockIdx.z] : 0.f;
    #pragma unroll
    for (int ma = 0; ma < 4; ma++) {
        int r = row0 + wm * 64 + ma * 16 + (lane >> 2);
        float q2v0 = 0.f, q2v1 = 0.f, cr0 = 0.f, cr1 = 0.f;
        if (DIST) {
            q2v0 = q2p[r]; q2v1 = q2p[r + 8];
            cr0 = sqrtf(q2v0 + km); cr1 = sqrtf(q2v1 + km);
        }
        #pragma unroll
        for (int na = 0; na < 4; na++) {
            int cc = col0 + wn * 32 + na * 8 + 2 * (lane & 3);
            float c0 = acc[ma][na][0], c1 = acc[ma][na][1];
            float c2 = acc[ma][na][2], c3 = acc[ma][na][3];
            if (DIST) {
                float k2v0 = k2p[cc], k2v1 = k2p[cc + 1];
                c0 = sqrtf(fmaxf(q2v0 + k2v0 - 2.f * c0, 0.f)) - cr0;
                c1 = sqrtf(fmaxf(q2v0 + k2v1 - 2.f * c1, 0.f)) - cr0;
                c2 = sqrtf(fmaxf(q2v1 + k2v0 - 2.f * c2, 0.f)) - cr1;
                c3 = sqrtf(fmaxf(q2v1 + k2v1 - 2.f * c3, 0.f)) - cr1;
            }
            if (RELU) {
                c0 = fmaxf(c0, 0.f); c1 = fmaxf(c1, 0.f);
                c2 = fmaxf(c2, 0.f); c3 = fmaxf(c3, 0.f);
            }
            if (sizeof(TOUT) == 2) {
                *(__half2*)((__half*)C + (long)r * Nc + cc) =
                    __floats2half2_rn(c0, c1);
                *(__half2*)((__half*)C + (long)(r + 8) * Nc + cc) =
                    __floats2half2_rn(c2, c3);
            } else {
                *(float2*)((float*)C + (long)r * Nc + cc) = make_float2(c0, c1);
                *(float2*)((float*)C + (long)(r + 8) * Nc + cc) = make_float2(c2, c3);
            }
        }
    }
}

// ---------------------------------------------------------------------------
// Conversion / transpose kernels
// ---------------------------------------------------------------------------
__global__ __launch_bounds__(256) void conv_f2h(
    const float* __restrict__ in, __half* __restrict__ out)
{
    long i = ((long)blockIdx.x * 256 + threadIdx.x) * 4;
    float4 v = *(const float4*)(in + i);
    *(__half2*)(out + i)     = __floats2half2_rn(v.x, v.y);
    *(__half2*)(out + i + 2) = __floats2half2_rn(v.z, v.w);
}

// x -> xh, and also into the left half of h = [x | ln1] (fp16)
__global__ __launch_bounds__(256) void conv_x_pack(
    const float* __restrict__ in, __half* __restrict__ xh,
    __half* __restrict__ hh)
{
    long i = ((long)blockIdx.x * 256 + threadIdx.x) * 4;
    float4 v = *(const float4*)(in + i);
    __half2 h0 = __floats2half2_rn(v.x, v.y);
    __half2 h1 = __floats2half2_rn(v.z, v.w);
    *(__half2*)(xh + i) = h0;
    *(__half2*)(xh + i + 2) = h1;
    long row = i >> 9;          // /512
    int col = (int)(i & 511);
    __half* hr = hh + row * (2 * DD) + col;
    *(__half2*)hr = h0;
    *(__half2*)(hr + 2) = h1;
}

// All 6 weight transposes (f32 -> f16, [R,C] -> [C,R]) in ONE launch.
struct TransArr {
    const float* in[6];
    __half* out[6];
    int R[6], C[6], start[6];   // start[i] = first flat tile index of matrix i
};

__global__ void trans_many(TransArr ta)
{
    __shared__ float t[32][33];
    int idx = blockIdx.x;
    int m = 0;
    while (m < 5 && idx >= ta.start[m + 1]) m++;
    int local = idx - ta.start[m];
    const int R = ta.R[m], C = ta.C[m];
    const int tpc = C >> 5;               // tiles along C
    int c0 = (local % tpc) << 5;
    int r0 = (local / tpc) << 5;
    const float* in = ta.in[m];
    __half* out = ta.out[m];

    #pragma unroll
    for (int i = threadIdx.y; i < 32; i += 8)
        t[i][threadIdx.x] = in[(long)(r0 + i) * C + c0 + threadIdx.x];
    __syncthreads();
    #pragma unroll
    for (int i = threadIdx.y; i < 32; i += 8)
        out[(long)(c0 + i) * R + r0 + threadIdx.x] =
            __float2half_rn(t[threadIdx.x][i]);
}

__global__ void trans_h2h(const __half* __restrict__ in, __half* __restrict__ out,
                          int R, int C)
{
    __shared__ __half t[32][33];
    long bi = (long)blockIdx.z * R * C;
    int c0 = blockIdx.x * 32, r0 = blockIdx.y * 32;
    #pragma unroll
    for (int i = threadIdx.y; i < 32; i += 8)
        t[i][threadIdx.x] = in[bi + (long)(r0 + i) * C + c0 + threadIdx.x];
    __syncthreads();
    #pragma unroll
    for (int i = threadIdx.y; i < 32; i += 8)
        out[bi + (long)(c0 + i) * R + r0 + threadIdx.x] = t[threadIdx.x][i];
}

// ---------------------------------------------------------------------------
// Reductions
// ---------------------------------------------------------------------------
__device__ __forceinline__ float warpSum(float v) {
    #pragma unroll
    for (int o = 16; o > 0; o >>= 1) v += __shfl_xor_sync(0xffffffffu, v, o);
    return v;
}
__device__ __forceinline__ float warpMax(float v) {
    #pragma unroll
    for (int o = 16; o > 0; o >>= 1) v = fmaxf(v, __shfl_xor_sync(0xffffffffu, v, o));
    return v;
}
__device__ float blockSum(float v) {
    __shared__ float sh[8];
    __shared__ float tot;
    __syncthreads();
    int lane = threadIdx.x & 31, w = threadIdx.x >> 5;
    v = warpSum(v);
    if (lane == 0) sh[w] = v;
    __syncthreads();
    if (w == 0) {
        float t = (threadIdx.x < (blockDim.x >> 5)) ? sh[threadIdx.x] : 0.f;
        t = warpSum(t);
        if (threadIdx.x == 0) tot = t;
    }
    __syncthreads();
    return tot;
}
__device__ float blockMax(float v) {
    __shared__ float sh[8];
    __shared__ float tot;
    __syncthreads();
    int lane = threadIdx.x & 31, w = threadIdx.x >> 5;
    v = warpMax(v);
    if (lane == 0) sh[w] = v;
    __syncthreads();
    if (w == 0) {
        float t = (threadIdx.x < (blockDim.x >> 5)) ? sh[threadIdx.x] : -INFINITY;
        t = warpMax(t);
        if (threadIdx.x == 0) tot = t;
    }
    __syncthreads();
    return tot;
}

// ---------------------------------------------------------------------------
// Elementwise kernels
// ---------------------------------------------------------------------------
// Row squared norms for q (rows [0,MQ)) and k (rows [MQ, MQ+MKV)) in one grid.
__global__ __launch_bounds__(256) void rownorm2_h(
    const __half* __restrict__ Q, const __half* __restrict__ Kk,
    float* __restrict__ q2, float* __restrict__ k2)
{
    const int row = blockIdx.x;
    const __half2* x;
    float* o;
    if (row < MQ) { x = (const __half2*)(Q + (long)row * DD); o = q2 + row; }
    else { x = (const __half2*)(Kk + (long)(row - MQ) * DD); o = k2 + (row - MQ); }
    float2 f = __half22float2(x[threadIdx.x]);
    float s = blockSum(f.x * f.x + f.y * f.y);
    if (threadIdx.x == 0) *o = s;
}

// per-batch mean of k2
__global__ __launch_bounds__(256) void k2mean_k(
    const float* __restrict__ k2, float* __restrict__ k2m)
{
    const float* kk = k2 + (long)blockIdx.x * SK;
    float s = 0.f;
    #pragma unroll
    for (int i = 0; i < SK / 256; i++) s += kk[threadIdx.x + i * 256];
    s = blockSum(s);
    if (threadIdx.x == 0) k2m[blockIdx.x] = s * (1.f / SK);
}

// softmax over fp16 shifted-dist row (in place)
__global__ __launch_bounds__(256) void softmax_k(__half* __restrict__ dist)
{
    __half2* row = (__half2*)(dist + (long)blockIdx.x * SK);

    float d[16];
    float mx = -INFINITY;
    #pragma unroll
    for (int i = 0; i < 8; i++) {
        int j = threadIdx.x + i * 256;
        float2 f = __half22float2(row[j]);
        d[2 * i] = f.x; d[2 * i + 1] = f.y;
        mx = fmaxf(mx, fmaxf(f.x, f.y));
    }
    mx = blockMax(mx);

    float s = 0.f;
    #pragma unroll
    for (int i = 0; i < 16; i++) {
        d[i] = expf(d[i] - mx);
        s += d[i];
    }
    s = blockSum(s);
    float inv = 1.f / s;
    #pragma unroll
    for (int i = 0; i < 8; i++) {
        int j = threadIdx.x + i * 256;
        row[j] = __floats2half2_rn(d[2 * i] * inv, d[2 * i + 1] * inv);
    }
}

// LayerNorm(mm) -> right half of h (left half pre-filled by conv_x_pack)
__global__ __launch_bounds__(256) void ln1_pack_k(
    const float* __restrict__ mm,
    const float* __restrict__ g, const float* __restrict__ b,
    __half* __restrict__ h)
{
    const int row = blockIdx.x;
    const float* m = mm + (long)row * DD;
    const int c0 = threadIdx.x, c1 = threadIdx.x + 256;
    float v0 = m[c0], v1 = m[c1];
    float mean = blockSum(v0 + v1) * (1.f / DD);
    float var  = blockSum(v0 * v0 + v1 * v1) * (1.f / DD) - mean * mean;
    float inv = rsqrtf(var + LN_EPS);

    __half* hr = h + (long)row * (2 * DD);
    hr[DD + c0] = __float2half_rn((v0 - mean) * inv * g[c0] + b[c0]);
    hr[DD + c1] = __float2half_rn((v1 - mean) * inv * g[c1] + b[c1]);
}

__global__ __launch_bounds__(256) void ln2_add_k(
    const float* __restrict__ t, const float* __restrict__ x,
    const float* __restrict__ g, const float* __restrict__ b,
    float* __restrict__ out)
{
    const int row = blockIdx.x;
    const float* tr = t + (long)row * DD;
    const int c0 = threadIdx.x, c1 = threadIdx.x + 256;
    float v0 = tr[c0], v1 = tr[c1];
    float mean = blockSum(v0 + v1) * (1.f / DD);
    float var  = blockSum(v0 * v0 + v1 * v1) * (1.f / DD) - mean * mean;
    float inv = rsqrtf(var + LN_EPS);

    const float* xr = x + (long)row * DD;
    float* orow = out + (long)row * DD;
    orow[c0] = xr[c0] + (v0 - mean) * inv * g[c0] + b[c0];
    orow[c1] = xr[c1] + (v1 - mean) * inv * g[c1] + b[c1];
}

// ---------------------------------------------------------------------------
// Launch
// ---------------------------------------------------------------------------
extern "C" void kernel_launch(void* const* d_in, const int* in_sizes, int n_in,
                              void* d_out, int out_size)
{
    const float* x   = (const float*)d_in[0];
    const float* src = (const float*)d_in[1];
    const float* Wq  = (const float*)d_in[2];
    const float* Wk  = (const float*)d_in[3];
    const float* Wv  = (const float*)d_in[4];
    const float* Wm  = (const float*)d_in[5];
    const float* W1  = (const float*)d_in[6];
    const float* W2  = (const float*)d_in[7];
    const float* g1  = (const float*)d_in[8];
    const float* b1  = (const float*)d_in[9];
    const float* g2  = (const float*)d_in[10];
    const float* b2  = (const float*)d_in[11];
    float* out = (float*)d_out;

    __half *xh, *srch, *qh, *kh, *vh, *vt, *sch, *msgh, *hh, *fc1h;
    __half *wqt, *wkt, *wvt, *wmt, *w1t, *w2t;
    float *tmp, *q2, *k2, *k2m;
    cudaGetSymbolAddress((void**)&xh,   g_xh);
    cudaGetSymbolAddress((void**)&srch, g_srch);
    cudaGetSymbolAddress((void**)&qh,   g_qh);
    cudaGetSymbolAddress((void**)&kh,   g_kh);
    cudaGetSymbolAddress((void**)&vh,   g_vh);
    cudaGetSymbolAddress((void**)&vt,   g_vt);
    cudaGetSymbolAddress((void**)&sch,  g_sch);
    cudaGetSymbolAddress((void**)&msgh, g_msgh);
    cudaGetSymbolAddress((void**)&hh,   g_hh);
    cudaGetSymbolAddress((void**)&fc1h, g_fc1h);
    cudaGetSymbolAddress((void**)&wqt,  g_wqt);
    cudaGetSymbolAddress((void**)&wkt,  g_wkt);
    cudaGetSymbolAddress((void**)&wvt,  g_wvt);
    cudaGetSymbolAddress((void**)&wmt,  g_wmt);
    cudaGetSymbolAddress((void**)&w1t,  g_w1t);
    cudaGetSymbolAddress((void**)&w2t,  g_w2t);
    cudaGetSymbolAddress((void**)&tmp,  g_tmp);
    cudaGetSymbolAddress((void**)&q2,   g_q2);
    cudaGetSymbolAddress((void**)&k2,   g_k2);
    cudaGetSymbolAddress((void**)&k2m,  g_k2m);

    cudaFuncSetAttribute((const void*)hgemm<false, __half, false>,
        cudaFuncAttributeMaxDynamicSharedMemorySize, SMEM_GEMM);
    cudaFuncSetAttribute((const void*)hgemm<false, float, false>,
        cudaFuncAttributeMaxDynamicSharedMemorySize, SMEM_GEMM);
    cudaFuncSetAttribute((const void*)hgemm<true, __half, false>,
        cudaFuncAttributeMaxDynamicSharedMemorySize, SMEM_GEMM);
    cudaFuncSetAttribute((const void*)hgemm<false, __half, true>,
        cudaFuncAttributeMaxDynamicSharedMemorySize, SMEM_GEMM);

    dim3 t32(32, 8, 1);

    // Conversions
    conv_f2h<<<(MKV * DD) / 1024, 256>>>(src, srch);
    conv_x_pack<<<(MQ * DD) / 1024, 256>>>(x, xh, hh);

    // All 6 weight transposes in one launch.
    // Tile counts: Wk/Wq/Wv/Wm = 256 each, W1 = 1024, W2 = 512; total 2560.
    TransArr ta;
    ta.in[0] = Wk; ta.out[0] = wkt; ta.R[0] = DD;     ta.C[0] = DD;
    ta.in[1] = Wq; ta.out[1] = wqt; ta.R[1] = DD;     ta.C[1] = DD;
    ta.in[2] = Wv; ta.out[2] = wvt; ta.R[2] = DD;     ta.C[2] = DD;
    ta.in[3] = Wm; ta.out[3] = wmt; ta.R[3] = DD;     ta.C[3] = DD;
    ta.in[4] = W1; ta.out[4] = w1t; ta.R[4] = 2 * DD; ta.C[4] = 2 * DD;
    ta.in[5] = W2; ta.out[5] = w2t; ta.R[5] = 2 * DD; ta.C[5] = DD;
    ta.start[0] = 0;    ta.start[1] = 256;  ta.start[2] = 512;
    ta.start[3] = 768;  ta.start[4] = 1024; ta.start[5] = 2048;
    trans_many<<<2560, t32>>>(ta);

    // Projections
    hgemm<false, __half, false><<<dim3(DD / 128, MKV / 128, 1), 256, SMEM_GEMM>>>(
        srch, wkt, kh, MKV, DD, DD, 0, 0, 0, nullptr, nullptr, nullptr);
    hgemm<false, __half, false><<<dim3(DD / 128, MQ / 128, 1), 256, SMEM_GEMM>>>(
        xh, wqt, qh, MQ, DD, DD, 0, 0, 0, nullptr, nullptr, nullptr);
    hgemm<false, __half, false><<<dim3(DD / 128, MKV / 128, 1), 256, SMEM_GEMM>>>(
        srch, wvt, vh, MKV, DD, DD, 0, 0, 0, nullptr, nullptr, nullptr);

    // Row squared norms for q and k in one launch, then per-batch k2 mean
    rownorm2_h<<<MQ + MKV, 256>>>(qh, kh, q2, k2);
    k2mean_k<<<NB, 256>>>(k2, k2m);

    // v transpose per batch: [S,D] -> [D,S]
    trans_h2h<<<dim3(DD / 32, SK / 32, NB), t32>>>(vh, vt, SK, DD);

    // Shifted dist fused into scores GEMM (fp16 out)
    hgemm<false, __half, true><<<dim3(SK / 128, LQ / 128, NB), 256, SMEM_GEMM>>>(
        qh, kh, sch, LQ, SK, DD,
        (long)LQ * DD, (long)SK * DD, (long)LQ * SK, q2, k2, k2m);

    // softmax in place -> fp16 attn
    softmax_k<<<MQ, 256>>>(sch);

    // message = attn @ v  (NT with vt, fp16 out)
    hgemm<false, __half, false><<<dim3(DD / 128, LQ / 128, NB), 256, SMEM_GEMM>>>(
        sch, vt, msgh, LQ, DD, SK,
        (long)LQ * SK, (long)DD * SK, (long)LQ * DD, nullptr, nullptr, nullptr);

    // mm = message @ Wm (fp32 out)
    hgemm<false, float, false><<<dim3(DD / 128, MQ / 128, 1), 256, SMEM_GEMM>>>(
        msgh, wmt, tmp, MQ, DD, DD, 0, 0, 0, nullptr, nullptr, nullptr);

    // h right half = LayerNorm(mm)
    ln1_pack_k<<<MQ, 256>>>(tmp, g1, b1, hh);

    // fc1 = relu(h @ W1) (fp16 out)
    hgemm<true, __half, false><<<dim3(2 * DD / 128, MQ / 128, 1), 256, SMEM_GEMM>>>(
        hh, w1t, fc1h, MQ, 2 * DD, 2 * DD, 0, 0, 0, nullptr, nullptr, nullptr);

    // fc2 = fc1 @ W2 (fp32 out)
    hgemm<false, float, false><<<dim3(DD / 128, MQ / 128, 1), 256, SMEM_GEMM>>>(
        fc1h, w2t, tmp, MQ, DD, 2 * DD, 0, 0, 0, nullptr, nullptr, nullptr);

    // out = x + LayerNorm(fc2)
    ln2_add_k<<<MQ, 256>>>(tmp, x, g2, b2, out);
}